// round 11
// baseline (speedup 1.0000x reference)
#include <cuda_runtime.h>
#include <math.h>

#define NB   4
#define NL   2048
#define ND   512
#define NH   8
#define NDK  64
#define NM   (NB*NL)   /* 8192 */

// Scratch (static __device__ arrays — allocation-free per harness rules)
__device__ float g_Q[NM*ND];    // (B,H,L,dk)
__device__ float g_K[NM*ND];    // (B,H,L,dk)
__device__ float g_V[NM*ND];    // (B,H,L,dk)
__device__ float g_att[NM*ND];  // (B,L,D)

// ---------------------------------------------------------------------------
// TF32 / cp.async helpers
// ---------------------------------------------------------------------------
__device__ __forceinline__ unsigned f2tf(float f) {
    unsigned u;
    asm("cvt.rna.tf32.f32 %0, %1;" : "=r"(u) : "f"(f));
    return u;
}

__device__ __forceinline__ void cpa16(float* sptr, const float* gptr) {
    unsigned s = (unsigned)__cvta_generic_to_shared(sptr);
    asm volatile("cp.async.cg.shared.global [%0], [%1], 16;" :: "r"(s), "l"(gptr));
}
__device__ __forceinline__ void cpa_commit() {
    asm volatile("cp.async.commit_group;" ::: "memory");
}
__device__ __forceinline__ void cpa_wait3() {
    asm volatile("cp.async.wait_group 3;" ::: "memory");
}
__device__ __forceinline__ void cpa_wait2() {
    asm volatile("cp.async.wait_group 2;" ::: "memory");
}
__device__ __forceinline__ void cpa_wait1() {
    asm volatile("cp.async.wait_group 1;" ::: "memory");
}
__device__ __forceinline__ void cpa_wait0() {
    asm volatile("cp.async.wait_group 0;" ::: "memory");
}

// D(16x8) += A(16x8) * B(8x8), tf32 inputs, fp32 accumulate.
// Lane mapping (g = lane>>2, t = lane&3):
//  A: a0=(g,t) a1=(g+8,t) a2=(g,t+4) a3=(g+8,t+4)   [row, k]
//  B: b0=(t,g) b1=(t+4,g)                            [k, n]
//  D: c0=(g,2t) c1=(g,2t+1) c2=(g+8,2t) c3=(g+8,2t+1)
__device__ __forceinline__ void mma8(float* d, const unsigned* a, const unsigned* b) {
    asm volatile("mma.sync.aligned.m16n8k8.row.col.f32.tf32.tf32.f32 "
                 "{%0,%1,%2,%3}, {%4,%5,%6,%7}, {%8,%9}, {%0,%1,%2,%3};"
                 : "+f"(d[0]), "+f"(d[1]), "+f"(d[2]), "+f"(d[3])
                 : "r"(a[0]), "r"(a[1]), "r"(a[2]), "r"(a[3]),
                   "r"(b[0]), "r"(b[1]));
}

// ---------------------------------------------------------------------------
// GEMM (tensor, 4-stage cp.async pipeline): Y = X @ W^T.
// X: (NM,512), W: (512,512), row-major fp32. Block tile (MT*64)m x 64n,
// K-chunk 16 (32 chunks), 4 smem buffers, prefetch distance 3.
// 8 warps in 4(m) x 2(n), warp tile (MT*16) x 32.
// One __syncthreads per chunk; stage is issued AFTER the barrier so its
// cp.async writes cannot race the previous chunk's readers.
// mode 0: Y[m*512+n]; mode 1: (B,H,L,dk) scatter, h = blockIdx.x.
// ---------------------------------------------------------------------------
#define GST 20   /* 16 + 4 pad: (20g+t) mod 32 distinct across warp */

template<int MT>
__device__ __forceinline__
void gemm_body(const float* __restrict__ X, const float* __restrict__ W,
               float* __restrict__ Y, int mode)
{
    constexpr int BM = MT * 64;
    extern __shared__ float smem[];
    float* Xs0 = smem;                     // 4 x BM*GST
    float* Ws0 = smem + 4 * BM * GST;      // 4 x 64*GST

    const int tid  = threadIdx.x;
    const int w    = tid >> 5, lane = tid & 31;
    const int g    = lane >> 2, t = lane & 3;
    const int wm   = w & 3, wn = w >> 2;
    const int m0   = blockIdx.y * BM, n0 = blockIdx.x * 64;

    float acc[MT][4][4];
    #pragma unroll
    for (int mt = 0; mt < MT; mt++)
        #pragma unroll
        for (int nt = 0; nt < 4; nt++)
            #pragma unroll
            for (int i = 0; i < 4; i++) acc[mt][nt][i] = 0.f;

    // async stage of one k16 chunk c into buffer c&3
    auto stage = [&](int c) {
        int buf = c & 3;
        float* Xs = Xs0 + buf * BM * GST;
        float* Ws = Ws0 + buf * 64 * GST;
        int k0 = c * 16;
        #pragma unroll
        for (int i = 0; i < MT; i++) {               // BM*4 16B-chunks / 256 thr
            int idx = tid + 256 * i;
            int r = idx >> 2, cc = (idx & 3) * 4;
            cpa16(&Xs[r * GST + cc], &X[(size_t)(m0 + r) * 512 + k0 + cc]);
        }
        {                                             // 256 chunks / 256 thr
            int r = tid >> 2, cc = (tid & 3) * 4;
            cpa16(&Ws[r * GST + cc], &W[(size_t)(n0 + r) * 512 + k0 + cc]);
        }
        cpa_commit();
    };

    stage(0); stage(1); stage(2);

    for (int c = 0; c < 32; c++) {
        __syncthreads();                  // all warps past compute(c-1)
        if (c + 3 < 32) { stage(c + 3); cpa_wait3(); }
        else if (c == 29) cpa_wait2();
        else if (c == 30) cpa_wait1();
        else              cpa_wait0();

        const float* Xs = Xs0 + (c & 3) * BM * GST;
        const float* Ws = Ws0 + (c & 3) * 64 * GST;

        #pragma unroll
        for (int ks = 0; ks < 2; ks++) {
            unsigned a[MT][4], bb[4][2];
            #pragma unroll
            for (int mt = 0; mt < MT; mt++) {
                const float* p = &Xs[(wm * (MT * 16) + mt * 16 + g) * GST + ks * 8 + t];
                a[mt][0] = f2tf(p[0]);
                a[mt][1] = f2tf(p[8 * GST]);
                a[mt][2] = f2tf(p[4]);
                a[mt][3] = f2tf(p[8 * GST + 4]);
            }
            #pragma unroll
            for (int nt = 0; nt < 4; nt++) {
                const float* p = &Ws[(wn * 32 + nt * 8 + g) * GST + ks * 8 + t];
                bb[nt][0] = f2tf(p[0]);
                bb[nt][1] = f2tf(p[4]);
            }
            #pragma unroll
            for (int mt = 0; mt < MT; mt++)
                #pragma unroll
                for (int nt = 0; nt < 4; nt++)
                    mma8(acc[mt][nt], a[mt], bb[nt]);
        }
    }

    // Epilogue
    #pragma unroll
    for (int mt = 0; mt < MT; mt++) {
        int row = m0 + wm * (MT * 16) + mt * 16 + g;
        #pragma unroll
        for (int nt = 0; nt < 4; nt++) {
            int off = wn * 32 + nt * 8 + 2 * t;      // 0..63 within n-block
            float2 v0 = make_float2(acc[mt][nt][0], acc[mt][nt][1]);
            float2 v1 = make_float2(acc[mt][nt][2], acc[mt][nt][3]);
            if (mode == 0) {
                float* p = &Y[(size_t)row * 512 + n0 + off];
                *(float2*)p = v0;
                *(float2*)(p + (size_t)8 * 512) = v1;
            } else {
                int b = row >> 11, l = row & 2047, h = blockIdx.x;
                size_t base = ((size_t)((b * 8 + h) * 2048 + l)) * 64 + off;
                *(float2*)&Y[base] = v0;
                *(float2*)&Y[base + (size_t)8 * 64] = v1;
            }
        }
    }
}

#define SMEM_GEMM4 (4 * (256 * GST + 64 * GST) * 4)   /* 102400 B */
#define SMEM_GEMM2 (4 * (128 * GST + 64 * GST) * 4)   /*  61440 B */

// Fused Q/K/V projection: gridDim.z = 3 selects the weight + destination.
__global__ __launch_bounds__(256)
void gemm_qkv(const float* __restrict__ X,
              const float* __restrict__ Wq, const float* __restrict__ Wk,
              const float* __restrict__ Wv,
              float* __restrict__ Qp, float* __restrict__ Kp, float* __restrict__ Vp)
{
    const float* W = (blockIdx.z == 0) ? Wq : (blockIdx.z == 1) ? Wk : Wv;
    float*       Y = (blockIdx.z == 0) ? Qp : (blockIdx.z == 1) ? Kp : Vp;
    gemm_body<4>(X, W, Y, 1);
}

__global__ __launch_bounds__(256)
void gemm_out(const float* __restrict__ X, const float* __restrict__ W,
              float* __restrict__ Y)
{
    gemm_body<2>(X, W, Y, 0);
}

// ---------------------------------------------------------------------------
// Wave attention (tensor, cp.async double-buffered K/V): 128 q-rows per
// block, 4 warps (32 rows each as 2 m-tiles), stream 64-key tiles.
// FIXED-MAX softmax: scores are bounded (|s| <~ 8), so p = exp(s) with a
// single end normalization is exact; removes max reductions, Oc rescales,
// and per-tile sum reductions (row sums accumulate per-thread, reduced once
// in the epilogue).
// P never touches smem: S D-fragments permuted to PV A-fragments by shuffle.
// Smem floats: Ks[2][64*68], Vs[2][64*72], wave[2048] = 79872 B -> 2 blk/SM.
// ---------------------------------------------------------------------------
#define KS_ST 68
#define VS_ST 72
#define SM_VS   (2 * 64 * KS_ST)
#define SM_WAVE (SM_VS + 2 * 64 * VS_ST)
#define SMEM_ATTN ((SM_WAVE + 2048) * 4)

__global__ __launch_bounds__(128, 2)
void wave_attn_tc(const float* __restrict__ wfreq, const float* __restrict__ wphase)
{
    extern __shared__ float sm[];
    float* Ks0 = sm;
    float* Vs0 = sm + SM_VS;
    float* Wv  = sm + SM_WAVE;

    const int tid = threadIdx.x;
    const int w   = tid >> 5, lane = tid & 31;
    const int g   = lane >> 2, t = lane & 3;
    const int bh  = blockIdx.y, b = bh >> 3, h = bh & 7;
    const int q0  = blockIdx.x * 128;

    const float* Qg = g_Q + ((size_t)bh * NL + q0) * NDK;
    const float* Kg = g_K + (size_t)bh * NL * NDK;
    const float* Vg = g_V + (size_t)bh * NL * NDK;

    // async stage of K/V tile kt into buffer `buf` (raw fp32)
    auto stage_kv = [&](int kt, int buf) {
        float* Ksb = Ks0 + buf * 64 * KS_ST;
        float* Vsb = Vs0 + buf * 64 * VS_ST;
        #pragma unroll
        for (int i = 0; i < 8; i++) {
            int idx = tid + 128 * i;
            int r = idx >> 4, c = (idx & 15) * 4;
            const float* gk = &Kg[(size_t)(kt * 64 + r) * 64 + c];
            const float* gv = &Vg[(size_t)(kt * 64 + r) * 64 + c];
            cpa16(&Ksb[r * KS_ST + c], gk);
            cpa16(&Vsb[r * VS_ST + c], gv);
        }
        cpa_commit();
    };

    stage_kv(0, 0);   // tile 0 in flight while we do wave table + Q fragments

    // Wave table (once per block)
    {
        const float f = wfreq[h], ph = wphase[h];
        const float TWO_PI = 6.28318530717958647692f;
        for (int j = tid; j < NL; j += 128)
            Wv[j] = cosf(TWO_PI * f * (float)j + ph);
    }

    // Q A-fragments straight from gmem (scaled by dk^-1/2, one-time)
    unsigned Qa[2][8][4];
    #pragma unroll
    for (int mt = 0; mt < 2; mt++)
        #pragma unroll
        for (int ks = 0; ks < 8; ks++) {
            const float* qp = &Qg[(w * 32 + mt * 16 + g) * 64 + ks * 8 + t];
            Qa[mt][ks][0] = f2tf(qp[0]            * 0.125f);
            Qa[mt][ks][1] = f2tf(qp[8 * 64]       * 0.125f);
            Qa[mt][ks][2] = f2tf(qp[4]            * 0.125f);
            Qa[mt][ks][3] = f2tf(qp[8 * 64 + 4]   * 0.125f);
        }

    float Oc[2][8][4];
    #pragma unroll
    for (int mt = 0; mt < 2; mt++)
        #pragma unroll
        for (int nt = 0; nt < 8; nt++)
            #pragma unroll
            for (int i = 0; i < 4; i++) Oc[mt][nt][i] = 0.f;
    float lpA[2] = {0.f, 0.f}, lpB[2] = {0.f, 0.f};   // per-thread row sums

    const int srcA = (lane & 28) | (t >> 1);   // 4g + t/2
    const int srcB = srcA | 2;                 // 4g + t/2 + 2
    const bool odd = (t & 1);

    for (int kt = 0; kt < 32; kt++) {
        if (kt + 1 < 32) { stage_kv(kt + 1, (kt + 1) & 1); cpa_wait1(); }
        else             { cpa_wait0(); }
        __syncthreads();

        const float* Ksb = Ks0 + (kt & 1) * 64 * KS_ST;
        const float* Vsb = Vs0 + (kt & 1) * 64 * VS_ST;

        // S = Q @ K^T : both m-tiles share each B-fragment load (tf32 at read)
        float Sc[2][8][4];
        #pragma unroll
        for (int mt = 0; mt < 2; mt++)
            #pragma unroll
            for (int nt = 0; nt < 8; nt++)
                #pragma unroll
                for (int i = 0; i < 4; i++) Sc[mt][nt][i] = 0.f;
        #pragma unroll
        for (int ks = 0; ks < 8; ks++) {
            #pragma unroll
            for (int nt = 0; nt < 8; nt++) {
                unsigned bb[2];
                const float* p = &Ksb[(nt * 8 + g) * KS_ST + ks * 8 + t];
                bb[0] = f2tf(p[0]);
                bb[1] = f2tf(p[4]);
                mma8(Sc[0][nt], Qa[0][ks], bb);
                mma8(Sc[1][nt], Qa[1][ks], bb);
            }
        }

        // Wave modulation + fixed-max exp; accumulate per-thread row sums
        #pragma unroll
        for (int mt = 0; mt < 2; mt++) {
            #pragma unroll
            for (int nt = 0; nt < 8; nt++) {
                int col = kt * 64 + nt * 8 + 2 * t;
                float w0 = Wv[col], w1 = Wv[col + 1];
                float p0 = __expf(Sc[mt][nt][0] * w0);
                float p1 = __expf(Sc[mt][nt][1] * w1);
                float p2 = __expf(Sc[mt][nt][2] * w0);
                float p3 = __expf(Sc[mt][nt][3] * w1);
                lpA[mt] += p0 + p1;
                lpB[mt] += p2 + p3;
                Sc[mt][nt][0] = p0; Sc[mt][nt][1] = p1;
                Sc[mt][nt][2] = p2; Sc[mt][nt][3] = p3;
            }
        }

        // O += P @ V : P A-fragments built from Sc D-fragments by shuffle.
        // k-step ks of PV = n-block ks of S (cols ks*8..ks*8+7).
        #pragma unroll
        for (int ks = 0; ks < 8; ks++) {
            unsigned pa[2][4];
            #pragma unroll
            for (int mt = 0; mt < 2; mt++) {
                float p0 = Sc[mt][ks][0], p1 = Sc[mt][ks][1];
                float p2 = Sc[mt][ks][2], p3 = Sc[mt][ks][3];
                float x0 = __shfl_sync(0xffffffffu, p0, srcA);
                float x1 = __shfl_sync(0xffffffffu, p1, srcA);
                float x2 = __shfl_sync(0xffffffffu, p2, srcA);
                float x3 = __shfl_sync(0xffffffffu, p3, srcA);
                float y0 = __shfl_sync(0xffffffffu, p0, srcB);
                float y1 = __shfl_sync(0xffffffffu, p1, srcB);
                float y2 = __shfl_sync(0xffffffffu, p2, srcB);
                float y3 = __shfl_sync(0xffffffffu, p3, srcB);
                pa[mt][0] = f2tf(odd ? x1 : x0);
                pa[mt][1] = f2tf(odd ? x3 : x2);
                pa[mt][2] = f2tf(odd ? y1 : y0);
                pa[mt][3] = f2tf(odd ? y3 : y2);
            }
            #pragma unroll
            for (int nt = 0; nt < 8; nt++) {
                unsigned bb[2];
                const float* vp = &Vsb[(ks * 8 + t) * VS_ST + nt * 8 + g];
                bb[0] = f2tf(vp[0]);
                bb[1] = f2tf(vp[4 * VS_ST]);
                mma8(Oc[0][nt], pa[0], bb);
                mma8(Oc[1][nt], pa[1], bb);
            }
        }
        __syncthreads();   // before next tile's cp.async overwrites this buffer
    }

    // Epilogue: reduce row sums across the t-quad, normalize, write (B,L,D)
    #pragma unroll
    for (int mt = 0; mt < 2; mt++) {
        float sA = lpA[mt];
        sA += __shfl_xor_sync(0xffffffffu, sA, 1);
        sA += __shfl_xor_sync(0xffffffffu, sA, 2);
        float sB = lpB[mt];
        sB += __shfl_xor_sync(0xffffffffu, sB, 1);
        sB += __shfl_xor_sync(0xffffffffu, sB, 2);
        float iA = 1.f / sA, iB = 1.f / sB;

        int rowA = q0 + w * 32 + mt * 16 + g;
        size_t baseA = ((size_t)b * NL + rowA) * ND + h * NDK;
        size_t baseB = baseA + (size_t)8 * ND;
        #pragma unroll
        for (int nt = 0; nt < 8; nt++) {
            int cb = nt * 8 + 2 * t;
            *(float2*)&g_att[baseA + cb] =
                make_float2(Oc[mt][nt][0] * iA, Oc[mt][nt][1] * iA);
            *(float2*)&g_att[baseB + cb] =
                make_float2(Oc[mt][nt][2] * iB, Oc[mt][nt][3] * iB);
        }
    }
}

// ---------------------------------------------------------------------------
extern "C" void kernel_launch(void* const* d_in, const int* in_sizes, int n_in,
                              void* d_out, int out_size)
{
    (void)in_sizes; (void)n_in; (void)out_size;
    const float* x  = (const float*)d_in[0];
    const float* Wq = (const float*)d_in[1];
    const float* Wk = (const float*)d_in[2];
    const float* Wv = (const float*)d_in[3];
    const float* Wo = (const float*)d_in[4];
    const float* wf = (const float*)d_in[5];
    const float* wp = (const float*)d_in[6];
    float* out = (float*)d_out;

    float *Qp, *Kp, *Vp, *Ap;
    cudaGetSymbolAddress((void**)&Qp, g_Q);
    cudaGetSymbolAddress((void**)&Kp, g_K);
    cudaGetSymbolAddress((void**)&Vp, g_V);
    cudaGetSymbolAddress((void**)&Ap, g_att);

    cudaFuncSetAttribute(gemm_qkv, cudaFuncAttributeMaxDynamicSharedMemorySize, SMEM_GEMM4);
    cudaFuncSetAttribute(gemm_out, cudaFuncAttributeMaxDynamicSharedMemorySize, SMEM_GEMM2);
    cudaFuncSetAttribute(wave_attn_tc, cudaFuncAttributeMaxDynamicSharedMemorySize, SMEM_ATTN);

    dim3 ggrid(8, 32, 3);   // (N/64, M/256, qkv)
    gemm_qkv<<<ggrid, 256, SMEM_GEMM4>>>(x, Wq, Wk, Wv, Qp, Kp, Vp);

    wave_attn_tc<<<dim3(16, 32), 128, SMEM_ATTN>>>(wf, wp);

    gemm_out<<<dim3(8, 64), 256, SMEM_GEMM2>>>(Ap, Wo, out);
}

// round 12
// speedup vs baseline: 1.6697x; 1.6697x over previous
#include <cuda_runtime.h>
#include <math.h>

#define NB   4
#define NL   2048
#define ND   512
#define NH   8
#define NDK  64
#define NM   (NB*NL)   /* 8192 */

// Scratch (static __device__ arrays — allocation-free per harness rules)
__device__ float g_Q[NM*ND];    // (B,H,L,dk)
__device__ float g_K[NM*ND];    // (B,H,L,dk)
__device__ float g_V[NM*ND];    // (B,H,L,dk)
__device__ float g_att[NM*ND];  // (B,L,D)

// ---------------------------------------------------------------------------
// TF32 / cp.async helpers
// ---------------------------------------------------------------------------
__device__ __forceinline__ unsigned f2tf(float f) {
    unsigned u;
    asm("cvt.rna.tf32.f32 %0, %1;" : "=r"(u) : "f"(f));
    return u;
}

__device__ __forceinline__ void cpa16(float* sptr, const float* gptr) {
    unsigned s = (unsigned)__cvta_generic_to_shared(sptr);
    asm volatile("cp.async.cg.shared.global [%0], [%1], 16;" :: "r"(s), "l"(gptr));
}
__device__ __forceinline__ void cpa_commit() {
    asm volatile("cp.async.commit_group;" ::: "memory");
}
__device__ __forceinline__ void cpa_wait1() {
    asm volatile("cp.async.wait_group 1;" ::: "memory");
}
__device__ __forceinline__ void cpa_wait0() {
    asm volatile("cp.async.wait_group 0;" ::: "memory");
}

// D(16x8) += A(16x8) * B(8x8), tf32 inputs, fp32 accumulate.
// Lane mapping (g = lane>>2, t = lane&3):
//  A: a0=(g,t) a1=(g+8,t) a2=(g,t+4) a3=(g+8,t+4)   [row, k]
//  B: b0=(t,g) b1=(t+4,g)                            [k, n]
//  D: c0=(g,2t) c1=(g,2t+1) c2=(g+8,2t) c3=(g+8,2t+1)
__device__ __forceinline__ void mma8(float* d, const unsigned* a, const unsigned* b) {
    asm volatile("mma.sync.aligned.m16n8k8.row.col.f32.tf32.tf32.f32 "
                 "{%0,%1,%2,%3}, {%4,%5,%6,%7}, {%8,%9}, {%0,%1,%2,%3};"
                 : "+f"(d[0]), "+f"(d[1]), "+f"(d[2]), "+f"(d[3])
                 : "r"(a[0]), "r"(a[1]), "r"(a[2]), "r"(a[3]),
                   "r"(b[0]), "r"(b[1]));
}

// ---------------------------------------------------------------------------
// GEMM (tensor, cp.async double-buffered, K-chunk 32): Y = X @ W^T.
// X: (NM,512), W: (512,512), row-major fp32. Block tile (MT*64)m x 64n,
// 8 warps in 4(m) x 2(n), warp tile (MT*16) x 32.
// Smem holds raw fp32; tf32 conversion (cvt.rna) at fragment-load time.
// mode 0: Y[m*512+n]; mode 1: (B,H,L,dk) scatter, h = blockIdx.x.
// (Reverted to the round-7 structure — the K16/4-stage variant regressed.)
// ---------------------------------------------------------------------------
#define XS_ST 36
#define WS_ST 36

template<int MT>
__device__ __forceinline__
void gemm_body(const float* __restrict__ X, const float* __restrict__ W,
               float* __restrict__ Y, int mode)
{
    constexpr int BM = MT * 64;
    extern __shared__ float smem[];
    float* Xs0 = smem;                       // 2 x BM*XS_ST
    float* Ws0 = smem + 2 * BM * XS_ST;      // 2 x 64*WS_ST

    const int tid  = threadIdx.x;
    const int w    = tid >> 5, lane = tid & 31;
    const int g    = lane >> 2, t = lane & 3;
    const int wm   = w & 3, wn = w >> 2;
    const int m0   = blockIdx.y * BM, n0 = blockIdx.x * 64;

    float acc[MT][4][4];
    #pragma unroll
    for (int mt = 0; mt < MT; mt++)
        #pragma unroll
        for (int nt = 0; nt < 4; nt++)
            #pragma unroll
            for (int i = 0; i < 4; i++) acc[mt][nt][i] = 0.f;

    // async stage of one K-chunk into buffer `buf`
    auto stage = [&](int k0, int buf) {
        float* Xs = Xs0 + buf * BM * XS_ST;
        float* Ws = Ws0 + buf * 64 * WS_ST;
        #pragma unroll
        for (int i = 0; i < MT * 2; i++) {           // BM*8 16B-chunks / 256 thr
            int idx = tid + 256 * i;
            int r = idx >> 3, c = (idx & 7) * 4;
            cpa16(&Xs[r * XS_ST + c], &X[(size_t)(m0 + r) * 512 + k0 + c]);
        }
        #pragma unroll
        for (int i = 0; i < 2; i++) {                // 512 chunks / 256 thr
            int idx = tid + 256 * i;
            int r = idx >> 3, c = (idx & 7) * 4;
            cpa16(&Ws[r * WS_ST + c], &W[(size_t)(n0 + r) * 512 + k0 + c]);
        }
        cpa_commit();
    };

    stage(0, 0);
    for (int kc = 0; kc < 16; kc++) {
        if (kc + 1 < 16) { stage((kc + 1) * 32, (kc + 1) & 1); cpa_wait1(); }
        else             { cpa_wait0(); }
        __syncthreads();

        const float* Xs = Xs0 + (kc & 1) * BM * XS_ST;
        const float* Ws = Ws0 + (kc & 1) * 64 * WS_ST;

        #pragma unroll
        for (int ks = 0; ks < 4; ks++) {
            unsigned a[MT][4], bb[4][2];
            #pragma unroll
            for (int mt = 0; mt < MT; mt++) {
                const float* p = &Xs[(wm * (MT * 16) + mt * 16 + g) * XS_ST + ks * 8 + t];
                a[mt][0] = f2tf(p[0]);
                a[mt][1] = f2tf(p[8 * XS_ST]);
                a[mt][2] = f2tf(p[4]);
                a[mt][3] = f2tf(p[8 * XS_ST + 4]);
            }
            #pragma unroll
            for (int nt = 0; nt < 4; nt++) {
                const float* p = &Ws[(wn * 32 + nt * 8 + g) * WS_ST + ks * 8 + t];
                bb[nt][0] = f2tf(p[0]);
                bb[nt][1] = f2tf(p[4]);
            }
            #pragma unroll
            for (int mt = 0; mt < MT; mt++)
                #pragma unroll
                for (int nt = 0; nt < 4; nt++)
                    mma8(acc[mt][nt], a[mt], bb[nt]);
        }
        __syncthreads();
    }

    // Epilogue
    #pragma unroll
    for (int mt = 0; mt < MT; mt++) {
        int row = m0 + wm * (MT * 16) + mt * 16 + g;
        #pragma unroll
        for (int nt = 0; nt < 4; nt++) {
            int off = wn * 32 + nt * 8 + 2 * t;      // 0..63 within n-block
            float2 v0 = make_float2(acc[mt][nt][0], acc[mt][nt][1]);
            float2 v1 = make_float2(acc[mt][nt][2], acc[mt][nt][3]);
            if (mode == 0) {
                float* p = &Y[(size_t)row * 512 + n0 + off];
                *(float2*)p = v0;
                *(float2*)(p + (size_t)8 * 512) = v1;
            } else {
                int b = row >> 11, l = row & 2047, h = blockIdx.x;
                size_t base = ((size_t)((b * 8 + h) * 2048 + l)) * 64 + off;
                *(float2*)&Y[base] = v0;
                *(float2*)&Y[base + (size_t)8 * 64] = v1;
            }
        }
    }
}

#define SMEM_GEMM4 ((2 * 256 * XS_ST + 2 * 64 * WS_ST) * 4)   /* 92160 B */
#define SMEM_GEMM2 ((2 * 128 * XS_ST + 2 * 64 * WS_ST) * 4)   /* 55296 B */

// Fused Q/K/V projection: gridDim.z = 3 selects the weight + destination.
__global__ __launch_bounds__(256)
void gemm_qkv(const float* __restrict__ X,
              const float* __restrict__ Wq, const float* __restrict__ Wk,
              const float* __restrict__ Wv,
              float* __restrict__ Qp, float* __restrict__ Kp, float* __restrict__ Vp)
{
    const float* W = (blockIdx.z == 0) ? Wq : (blockIdx.z == 1) ? Wk : Wv;
    float*       Y = (blockIdx.z == 0) ? Qp : (blockIdx.z == 1) ? Kp : Vp;
    gemm_body<4>(X, W, Y, 1);
}

__global__ __launch_bounds__(256)
void gemm_out(const float* __restrict__ X, const float* __restrict__ W,
              float* __restrict__ Y)
{
    gemm_body<2>(X, W, Y, 0);
}

// ---------------------------------------------------------------------------
// Wave attention (tensor, cp.async double-buffered K/V): 128 q-rows per
// block, 4 warps (32 rows each as 2 m-tiles), stream 64-key tiles.
// FIXED-MAX softmax: scores are bounded (|s| <~ 8), so p = exp(s) with a
// single end normalization is exact; removes max reductions, Oc rescales,
// and per-tile sum reductions (row sums accumulate per-thread, reduced once
// in the epilogue).
// P never touches smem: S D-fragments permuted to PV A-fragments by shuffle
// (col t <- lane 4g+(t>>1) comp t&1; col t+4 <- lane +2).
// Smem floats: Ks[2][64*68], Vs[2][64*72], wave[2048] = 79872 B -> 2 blk/SM.
// ---------------------------------------------------------------------------
#define KS_ST 68
#define VS_ST 72
#define SM_VS   (2 * 64 * KS_ST)
#define SM_WAVE (SM_VS + 2 * 64 * VS_ST)
#define SMEM_ATTN ((SM_WAVE + 2048) * 4)

__global__ __launch_bounds__(128, 2)
void wave_attn_tc(const float* __restrict__ wfreq, const float* __restrict__ wphase)
{
    extern __shared__ float sm[];
    float* Ks0 = sm;
    float* Vs0 = sm + SM_VS;
    float* Wv  = sm + SM_WAVE;

    const int tid = threadIdx.x;
    const int w   = tid >> 5, lane = tid & 31;
    const int g   = lane >> 2, t = lane & 3;
    const int bh  = blockIdx.y, b = bh >> 3, h = bh & 7;
    const int q0  = blockIdx.x * 128;

    const float* Qg = g_Q + ((size_t)bh * NL + q0) * NDK;
    const float* Kg = g_K + (size_t)bh * NL * NDK;
    const float* Vg = g_V + (size_t)bh * NL * NDK;

    // async stage of K/V tile kt into buffer `buf` (raw fp32)
    auto stage_kv = [&](int kt, int buf) {
        float* Ksb = Ks0 + buf * 64 * KS_ST;
        float* Vsb = Vs0 + buf * 64 * VS_ST;
        #pragma unroll
        for (int i = 0; i < 8; i++) {
            int idx = tid + 128 * i;
            int r = idx >> 4, c = (idx & 15) * 4;
            const float* gk = &Kg[(size_t)(kt * 64 + r) * 64 + c];
            const float* gv = &Vg[(size_t)(kt * 64 + r) * 64 + c];
            cpa16(&Ksb[r * KS_ST + c], gk);
            cpa16(&Vsb[r * VS_ST + c], gv);
        }
        cpa_commit();
    };

    stage_kv(0, 0);   // tile 0 in flight while we do wave table + Q fragments

    // Wave table (once per block)
    {
        const float f = wfreq[h], ph = wphase[h];
        const float TWO_PI = 6.28318530717958647692f;
        for (int j = tid; j < NL; j += 128)
            Wv[j] = cosf(TWO_PI * f * (float)j + ph);
    }

    // Q A-fragments straight from gmem (scaled by dk^-1/2, one-time)
    unsigned Qa[2][8][4];
    #pragma unroll
    for (int mt = 0; mt < 2; mt++)
        #pragma unroll
        for (int ks = 0; ks < 8; ks++) {
            const float* qp = &Qg[(w * 32 + mt * 16 + g) * 64 + ks * 8 + t];
            Qa[mt][ks][0] = f2tf(qp[0]            * 0.125f);
            Qa[mt][ks][1] = f2tf(qp[8 * 64]       * 0.125f);
            Qa[mt][ks][2] = f2tf(qp[4]            * 0.125f);
            Qa[mt][ks][3] = f2tf(qp[8 * 64 + 4]   * 0.125f);
        }

    float Oc[2][8][4];
    #pragma unroll
    for (int mt = 0; mt < 2; mt++)
        #pragma unroll
        for (int nt = 0; nt < 8; nt++)
            #pragma unroll
            for (int i = 0; i < 4; i++) Oc[mt][nt][i] = 0.f;
    float lpA[2] = {0.f, 0.f}, lpB[2] = {0.f, 0.f};   // per-thread row sums

    const int srcA = (lane & 28) | (t >> 1);   // 4g + t/2
    const int srcB = srcA | 2;                 // 4g + t/2 + 2
    const bool odd = (t & 1);

    for (int kt = 0; kt < 32; kt++) {
        if (kt + 1 < 32) { stage_kv(kt + 1, (kt + 1) & 1); cpa_wait1(); }
        else             { cpa_wait0(); }
        __syncthreads();

        const float* Ksb = Ks0 + (kt & 1) * 64 * KS_ST;
        const float* Vsb = Vs0 + (kt & 1) * 64 * VS_ST;

        // S = Q @ K^T : both m-tiles share each B-fragment load (tf32 at read)
        float Sc[2][8][4];
        #pragma unroll
        for (int mt = 0; mt < 2; mt++)
            #pragma unroll
            for (int nt = 0; nt < 8; nt++)
                #pragma unroll
                for (int i = 0; i < 4; i++) Sc[mt][nt][i] = 0.f;
        #pragma unroll
        for (int ks = 0; ks < 8; ks++) {
            #pragma unroll
            for (int nt = 0; nt < 8; nt++) {
                unsigned bb[2];
                const float* p = &Ksb[(nt * 8 + g) * KS_ST + ks * 8 + t];
                bb[0] = f2tf(p[0]);
                bb[1] = f2tf(p[4]);
                mma8(Sc[0][nt], Qa[0][ks], bb);
                mma8(Sc[1][nt], Qa[1][ks], bb);
            }
        }

        // Wave modulation + fixed-max exp; accumulate per-thread row sums
        #pragma unroll
        for (int mt = 0; mt < 2; mt++) {
            #pragma unroll
            for (int nt = 0; nt < 8; nt++) {
                int col = kt * 64 + nt * 8 + 2 * t;
                float w0 = Wv[col], w1 = Wv[col + 1];
                float p0 = __expf(Sc[mt][nt][0] * w0);
                float p1 = __expf(Sc[mt][nt][1] * w1);
                float p2 = __expf(Sc[mt][nt][2] * w0);
                float p3 = __expf(Sc[mt][nt][3] * w1);
                lpA[mt] += p0 + p1;
                lpB[mt] += p2 + p3;
                Sc[mt][nt][0] = p0; Sc[mt][nt][1] = p1;
                Sc[mt][nt][2] = p2; Sc[mt][nt][3] = p3;
            }
        }

        // O += P @ V : P A-fragments built from Sc D-fragments by shuffle.
        // k-step ks of PV = n-block ks of S (cols ks*8..ks*8+7).
        #pragma unroll
        for (int ks = 0; ks < 8; ks++) {
            unsigned pa[2][4];
            #pragma unroll
            for (int mt = 0; mt < 2; mt++) {
                float p0 = Sc[mt][ks][0], p1 = Sc[mt][ks][1];
                float p2 = Sc[mt][ks][2], p3 = Sc[mt][ks][3];
                float x0 = __shfl_sync(0xffffffffu, p0, srcA);
                float x1 = __shfl_sync(0xffffffffu, p1, srcA);
                float x2 = __shfl_sync(0xffffffffu, p2, srcA);
                float x3 = __shfl_sync(0xffffffffu, p3, srcA);
                float y0 = __shfl_sync(0xffffffffu, p0, srcB);
                float y1 = __shfl_sync(0xffffffffu, p1, srcB);
                float y2 = __shfl_sync(0xffffffffu, p2, srcB);
                float y3 = __shfl_sync(0xffffffffu, p3, srcB);
                pa[mt][0] = f2tf(odd ? x1 : x0);
                pa[mt][1] = f2tf(odd ? x3 : x2);
                pa[mt][2] = f2tf(odd ? y1 : y0);
                pa[mt][3] = f2tf(odd ? y3 : y2);
            }
            #pragma unroll
            for (int nt = 0; nt < 8; nt++) {
                unsigned bb[2];
                const float* vp = &Vsb[(ks * 8 + t) * VS_ST + nt * 8 + g];
                bb[0] = f2tf(vp[0]);
                bb[1] = f2tf(vp[4 * VS_ST]);
                mma8(Oc[0][nt], pa[0], bb);
                mma8(Oc[1][nt], pa[1], bb);
            }
        }
        __syncthreads();   // before next tile's cp.async overwrites this buffer
    }

    // Epilogue: reduce row sums across the t-quad, normalize, write (B,L,D)
    #pragma unroll
    for (int mt = 0; mt < 2; mt++) {
        float sA = lpA[mt];
        sA += __shfl_xor_sync(0xffffffffu, sA, 1);
        sA += __shfl_xor_sync(0xffffffffu, sA, 2);
        float sB = lpB[mt];
        sB += __shfl_xor_sync(0xffffffffu, sB, 1);
        sB += __shfl_xor_sync(0xffffffffu, sB, 2);
        float iA = 1.f / sA, iB = 1.f / sB;

        int rowA = q0 + w * 32 + mt * 16 + g;
        size_t baseA = ((size_t)b * NL + rowA) * ND + h * NDK;
        size_t baseB = baseA + (size_t)8 * ND;
        #pragma unroll
        for (int nt = 0; nt < 8; nt++) {
            int cb = nt * 8 + 2 * t;
            *(float2*)&g_att[baseA + cb] =
                make_float2(Oc[mt][nt][0] * iA, Oc[mt][nt][1] * iA);
            *(float2*)&g_att[baseB + cb] =
                make_float2(Oc[mt][nt][2] * iB, Oc[mt][nt][3] * iB);
        }
    }
}

// ---------------------------------------------------------------------------
extern "C" void kernel_launch(void* const* d_in, const int* in_sizes, int n_in,
                              void* d_out, int out_size)
{
    (void)in_sizes; (void)n_in; (void)out_size;
    const float* x  = (const float*)d_in[0];
    const float* Wq = (const float*)d_in[1];
    const float* Wk = (const float*)d_in[2];
    const float* Wv = (const float*)d_in[3];
    const float* Wo = (const float*)d_in[4];
    const float* wf = (const float*)d_in[5];
    const float* wp = (const float*)d_in[6];
    float* out = (float*)d_out;

    float *Qp, *Kp, *Vp, *Ap;
    cudaGetSymbolAddress((void**)&Qp, g_Q);
    cudaGetSymbolAddress((void**)&Kp, g_K);
    cudaGetSymbolAddress((void**)&Vp, g_V);
    cudaGetSymbolAddress((void**)&Ap, g_att);

    cudaFuncSetAttribute(gemm_qkv, cudaFuncAttributeMaxDynamicSharedMemorySize, SMEM_GEMM4);
    cudaFuncSetAttribute(gemm_out, cudaFuncAttributeMaxDynamicSharedMemorySize, SMEM_GEMM2);
    cudaFuncSetAttribute(wave_attn_tc, cudaFuncAttributeMaxDynamicSharedMemorySize, SMEM_ATTN);

    dim3 ggrid(8, 32, 3);   // (N/64, M/256, qkv)
    gemm_qkv<<<ggrid, 256, SMEM_GEMM4>>>(x, Wq, Wk, Wv, Qp, Kp, Vp);

    wave_attn_tc<<<dim3(16, 32), 128, SMEM_ATTN>>>(wf, wp);

    gemm_out<<<dim3(8, 64), 256, SMEM_GEMM2>>>(Ap, Wo, out);
}

// round 13
// speedup vs baseline: 2.6908x; 1.6115x over previous
#include <cuda_runtime.h>
#include <math.h>

#define NB   4
#define NL   2048
#define ND   512
#define NH   8
#define NDK  64
#define NM   (NB*NL)   /* 8192 */

// Scratch (static __device__ arrays — allocation-free per harness rules)
__device__ float g_Q[NM*ND];    // (B,H,L,dk)
__device__ float g_K[NM*ND];    // (B,H,L,dk)
__device__ float g_V[NM*ND];    // (B,H,L,dk)
__device__ float g_att[NM*ND];  // (B,L,D)

// ---------------------------------------------------------------------------
// fp16 / cp.async helpers
// ---------------------------------------------------------------------------
// pack two fp32 into f16x2 (lo = first arg). PTX: first src -> hi half.
__device__ __forceinline__ unsigned packh2(float lo, float hi) {
    unsigned r;
    asm("cvt.rn.f16x2.f32 %0, %1, %2;" : "=r"(r) : "f"(hi), "f"(lo));
    return r;
}

__device__ __forceinline__ void cpa16(float* sptr, const float* gptr) {
    unsigned s = (unsigned)__cvta_generic_to_shared(sptr);
    asm volatile("cp.async.cg.shared.global [%0], [%1], 16;" :: "r"(s), "l"(gptr));
}
__device__ __forceinline__ void cpa_commit() {
    asm volatile("cp.async.commit_group;" ::: "memory");
}
__device__ __forceinline__ void cpa_wait1() {
    asm volatile("cp.async.wait_group 1;" ::: "memory");
}
__device__ __forceinline__ void cpa_wait0() {
    asm volatile("cp.async.wait_group 0;" ::: "memory");
}

// D(16x8) += A(16x16) * B(16x8), fp16 inputs, fp32 accumulate.
// Lane mapping (g = lane>>2, t = lane&3), all pairs packed f16x2 (lo first):
//  A: a0=(g,2t:2t+1) a1=(g+8,2t:2t+1) a2=(g,2t+8:2t+9) a3=(g+8,2t+8:2t+9)
//  B: b0=(2t:2t+1, g) b1=(2t+8:2t+9, g)                 [k, n]
//  D: c0=(g,2t) c1=(g,2t+1) c2=(g+8,2t) c3=(g+8,2t+1)
__device__ __forceinline__ void mma16(float* d, const unsigned* a, const unsigned* b) {
    asm volatile("mma.sync.aligned.m16n8k16.row.col.f32.f16.f16.f32 "
                 "{%0,%1,%2,%3}, {%4,%5,%6,%7}, {%8,%9}, {%0,%1,%2,%3};"
                 : "+f"(d[0]), "+f"(d[1]), "+f"(d[2]), "+f"(d[3])
                 : "r"(a[0]), "r"(a[1]), "r"(a[2]), "r"(a[3]),
                   "r"(b[0]), "r"(b[1]));
}

// ---------------------------------------------------------------------------
// GEMM (fp16 tensor, cp.async double-buffered, K-chunk 32): Y = X @ W^T.
// X: (NM,512), W: (512,512), row-major fp32. Block tile (MT*64)m x 64n,
// 8 warps in 4(m) x 2(n), warp tile (MT*16) x 32. Smem raw fp32; fp16
// conversion (cvt.rn.f16x2) at fragment-load time via float2 LDS.
// Stride 40 (== 8 mod 32): LDS.64 bank index 4g+t distinct per phase.
// mode 0: Y[m*512+n]; mode 1: (B,H,L,dk) scatter, h = blockIdx.x.
// ---------------------------------------------------------------------------
#define GST 40

template<int MT>
__device__ __forceinline__
void gemm_body(const float* __restrict__ X, const float* __restrict__ W,
               float* __restrict__ Y, int mode)
{
    constexpr int BM = MT * 64;
    extern __shared__ float smem[];
    float* Xs0 = smem;                       // 2 x BM*GST
    float* Ws0 = smem + 2 * BM * GST;        // 2 x 64*GST

    const int tid  = threadIdx.x;
    const int w    = tid >> 5, lane = tid & 31;
    const int g    = lane >> 2, t = lane & 3;
    const int wm   = w & 3, wn = w >> 2;
    const int m0   = blockIdx.y * BM, n0 = blockIdx.x * 64;

    float acc[MT][4][4];
    #pragma unroll
    for (int mt = 0; mt < MT; mt++)
        #pragma unroll
        for (int nt = 0; nt < 4; nt++)
            #pragma unroll
            for (int i = 0; i < 4; i++) acc[mt][nt][i] = 0.f;

    // async stage of one K32 chunk into buffer `buf`
    auto stage = [&](int k0, int buf) {
        float* Xs = Xs0 + buf * BM * GST;
        float* Ws = Ws0 + buf * 64 * GST;
        #pragma unroll
        for (int i = 0; i < MT * 2; i++) {           // BM*8 16B-chunks / 256 thr
            int idx = tid + 256 * i;
            int r = idx >> 3, c = (idx & 7) * 4;
            cpa16(&Xs[r * GST + c], &X[(size_t)(m0 + r) * 512 + k0 + c]);
        }
        #pragma unroll
        for (int i = 0; i < 2; i++) {                // 512 chunks / 256 thr
            int idx = tid + 256 * i;
            int r = idx >> 3, c = (idx & 7) * 4;
            cpa16(&Ws[r * GST + c], &W[(size_t)(n0 + r) * 512 + k0 + c]);
        }
        cpa_commit();
    };

    stage(0, 0);
    for (int kc = 0; kc < 16; kc++) {
        if (kc + 1 < 16) { stage((kc + 1) * 32, (kc + 1) & 1); cpa_wait1(); }
        else             { cpa_wait0(); }
        __syncthreads();

        const float* Xs = Xs0 + (kc & 1) * BM * GST;
        const float* Ws = Ws0 + (kc & 1) * 64 * GST;

        #pragma unroll
        for (int ks = 0; ks < 2; ks++) {     // two k16 steps per K32 chunk
            unsigned a[MT][4], bb[4][2];
            #pragma unroll
            for (int mt = 0; mt < MT; mt++) {
                const float* p = &Xs[(wm * (MT * 16) + mt * 16 + g) * GST + ks * 16 + 2 * t];
                float2 l0 = *(const float2*)p;
                float2 l1 = *(const float2*)(p + 8 * GST);
                float2 h0 = *(const float2*)(p + 8);
                float2 h1 = *(const float2*)(p + 8 * GST + 8);
                a[mt][0] = packh2(l0.x, l0.y);
                a[mt][1] = packh2(l1.x, l1.y);
                a[mt][2] = packh2(h0.x, h0.y);
                a[mt][3] = packh2(h1.x, h1.y);
            }
            #pragma unroll
            for (int nt = 0; nt < 4; nt++) {
                const float* p = &Ws[(wn * 32 + nt * 8 + g) * GST + ks * 16 + 2 * t];
                float2 b0 = *(const float2*)p;
                float2 b1 = *(const float2*)(p + 8);
                bb[nt][0] = packh2(b0.x, b0.y);
                bb[nt][1] = packh2(b1.x, b1.y);
            }
            #pragma unroll
            for (int mt = 0; mt < MT; mt++)
                #pragma unroll
                for (int nt = 0; nt < 4; nt++)
                    mma16(acc[mt][nt], a[mt], bb[nt]);
        }
        __syncthreads();
    }

    // Epilogue
    #pragma unroll
    for (int mt = 0; mt < MT; mt++) {
        int row = m0 + wm * (MT * 16) + mt * 16 + g;
        #pragma unroll
        for (int nt = 0; nt < 4; nt++) {
            int off = wn * 32 + nt * 8 + 2 * t;      // 0..63 within n-block
            float2 v0 = make_float2(acc[mt][nt][0], acc[mt][nt][1]);
            float2 v1 = make_float2(acc[mt][nt][2], acc[mt][nt][3]);
            if (mode == 0) {
                float* p = &Y[(size_t)row * 512 + n0 + off];
                *(float2*)p = v0;
                *(float2*)(p + (size_t)8 * 512) = v1;
            } else {
                int b = row >> 11, l = row & 2047, h = blockIdx.x;
                size_t base = ((size_t)((b * 8 + h) * 2048 + l)) * 64 + off;
                *(float2*)&Y[base] = v0;
                *(float2*)&Y[base + (size_t)8 * 64] = v1;
            }
        }
    }
}

#define SMEM_GEMM4 ((2 * 256 * GST + 2 * 64 * GST) * 4)   /* 102400 B */
#define SMEM_GEMM2 ((2 * 128 * GST + 2 * 64 * GST) * 4)   /*  61440 B */

// Fused Q/K/V projection: gridDim.z = 3 selects the weight + destination.
__global__ __launch_bounds__(256)
void gemm_qkv(const float* __restrict__ X,
              const float* __restrict__ Wq, const float* __restrict__ Wk,
              const float* __restrict__ Wv,
              float* __restrict__ Qp, float* __restrict__ Kp, float* __restrict__ Vp)
{
    const float* W = (blockIdx.z == 0) ? Wq : (blockIdx.z == 1) ? Wk : Wv;
    float*       Y = (blockIdx.z == 0) ? Qp : (blockIdx.z == 1) ? Kp : Vp;
    gemm_body<4>(X, W, Y, 1);
}

__global__ __launch_bounds__(256)
void gemm_out(const float* __restrict__ X, const float* __restrict__ W,
              float* __restrict__ Y)
{
    gemm_body<2>(X, W, Y, 0);
}

// ---------------------------------------------------------------------------
// Wave attention (fp16 tensor, cp.async double-buffered K/V): 128 q-rows
// per block, 4 warps (32 rows each as 2 m-tiles), stream 64-key tiles.
// FIXED-MAX softmax (scores bounded: p = exp(s), end normalization).
// fp16 k16 A-fragment layout == fp32 D-fragment layout, so P moves from
// S-accumulators to PV A-fragments with PACKS ONLY — no shuffles, no smem.
// Strides: Ks 72 (LDS.64 conflict-free: 4g+t), Vs 68 (scalar 8t+g distinct).
// Smem floats: Ks[2][64*72], Vs[2][64*68], wave[2048] = 79872 B -> 2 blk/SM.
// ---------------------------------------------------------------------------
#define KS_ST 72
#define VS_ST 68
#define SM_VS   (2 * 64 * KS_ST)
#define SM_WAVE (SM_VS + 2 * 64 * VS_ST)
#define SMEM_ATTN ((SM_WAVE + 2048) * 4)

__global__ __launch_bounds__(128, 2)
void wave_attn_tc(const float* __restrict__ wfreq, const float* __restrict__ wphase)
{
    extern __shared__ float sm[];
    float* Ks0 = sm;
    float* Vs0 = sm + SM_VS;
    float* Wv  = sm + SM_WAVE;

    const int tid = threadIdx.x;
    const int w   = tid >> 5, lane = tid & 31;
    const int g   = lane >> 2, t = lane & 3;
    const int bh  = blockIdx.y, b = bh >> 3, h = bh & 7;
    const int q0  = blockIdx.x * 128;

    const float* Qg = g_Q + ((size_t)bh * NL + q0) * NDK;
    const float* Kg = g_K + (size_t)bh * NL * NDK;
    const float* Vg = g_V + (size_t)bh * NL * NDK;

    // async stage of K/V tile kt into buffer `buf` (raw fp32)
    auto stage_kv = [&](int kt, int buf) {
        float* Ksb = Ks0 + buf * 64 * KS_ST;
        float* Vsb = Vs0 + buf * 64 * VS_ST;
        #pragma unroll
        for (int i = 0; i < 8; i++) {
            int idx = tid + 128 * i;
            int r = idx >> 4, c = (idx & 15) * 4;
            const float* gk = &Kg[(size_t)(kt * 64 + r) * 64 + c];
            const float* gv = &Vg[(size_t)(kt * 64 + r) * 64 + c];
            cpa16(&Ksb[r * KS_ST + c], gk);
            cpa16(&Vsb[r * VS_ST + c], gv);
        }
        cpa_commit();
    };

    stage_kv(0, 0);   // tile 0 in flight while we do wave table + Q fragments

    // Wave table (once per block)
    {
        const float f = wfreq[h], ph = wphase[h];
        const float TWO_PI = 6.28318530717958647692f;
        for (int j = tid; j < NL; j += 128)
            Wv[j] = cosf(TWO_PI * f * (float)j + ph);
    }

    // Q A-fragments straight from gmem (scaled by dk^-1/2, packed fp16)
    unsigned Qa[2][4][4];
    #pragma unroll
    for (int mt = 0; mt < 2; mt++)
        #pragma unroll
        for (int ks = 0; ks < 4; ks++) {
            const float* qp = &Qg[(w * 32 + mt * 16 + g) * 64 + ks * 16 + 2 * t];
            Qa[mt][ks][0] = packh2(qp[0]       * 0.125f, qp[1]       * 0.125f);
            Qa[mt][ks][1] = packh2(qp[512]     * 0.125f, qp[513]     * 0.125f);
            Qa[mt][ks][2] = packh2(qp[8]       * 0.125f, qp[9]       * 0.125f);
            Qa[mt][ks][3] = packh2(qp[520]     * 0.125f, qp[521]     * 0.125f);
        }

    float Oc[2][8][4];
    #pragma unroll
    for (int mt = 0; mt < 2; mt++)
        #pragma unroll
        for (int nt = 0; nt < 8; nt++)
            #pragma unroll
            for (int i = 0; i < 4; i++) Oc[mt][nt][i] = 0.f;
    float lpA[2] = {0.f, 0.f}, lpB[2] = {0.f, 0.f};   // per-thread row sums

    for (int kt = 0; kt < 32; kt++) {
        if (kt + 1 < 32) { stage_kv(kt + 1, (kt + 1) & 1); cpa_wait1(); }
        else             { cpa_wait0(); }
        __syncthreads();

        const float* Ksb = Ks0 + (kt & 1) * 64 * KS_ST;
        const float* Vsb = Vs0 + (kt & 1) * 64 * VS_ST;

        // S = Q @ K^T : both m-tiles share each B-fragment load
        float Sc[2][8][4];
        #pragma unroll
        for (int mt = 0; mt < 2; mt++)
            #pragma unroll
            for (int nt = 0; nt < 8; nt++)
                #pragma unroll
                for (int i = 0; i < 4; i++) Sc[mt][nt][i] = 0.f;
        #pragma unroll
        for (int ks = 0; ks < 4; ks++) {
            #pragma unroll
            for (int nt = 0; nt < 8; nt++) {
                unsigned bb[2];
                const float* p = &Ksb[(nt * 8 + g) * KS_ST + ks * 16 + 2 * t];
                float2 k0 = *(const float2*)p;
                float2 k1 = *(const float2*)(p + 8);
                bb[0] = packh2(k0.x, k0.y);
                bb[1] = packh2(k1.x, k1.y);
                mma16(Sc[0][nt], Qa[0][ks], bb);
                mma16(Sc[1][nt], Qa[1][ks], bb);
            }
        }

        // Wave modulation + fixed-max exp; accumulate per-thread row sums
        #pragma unroll
        for (int mt = 0; mt < 2; mt++) {
            #pragma unroll
            for (int nt = 0; nt < 8; nt++) {
                int col = kt * 64 + nt * 8 + 2 * t;
                float w0 = Wv[col], w1 = Wv[col + 1];
                float p0 = __expf(Sc[mt][nt][0] * w0);
                float p1 = __expf(Sc[mt][nt][1] * w1);
                float p2 = __expf(Sc[mt][nt][2] * w0);
                float p3 = __expf(Sc[mt][nt][3] * w1);
                lpA[mt] += p0 + p1;
                lpB[mt] += p2 + p3;
                Sc[mt][nt][0] = p0; Sc[mt][nt][1] = p1;
                Sc[mt][nt][2] = p2; Sc[mt][nt][3] = p3;
            }
        }

        // O += P @ V : fp16 A-fragments are straight packs of the D-fragments
        // (a0 = (g,2t:2t+1) == {c0,c1}; a1 == {c2,c3}; a2/a3 from block 2ks+1).
        #pragma unroll
        for (int ks = 0; ks < 4; ks++) {
            unsigned pa[2][4];
            #pragma unroll
            for (int mt = 0; mt < 2; mt++) {
                pa[mt][0] = packh2(Sc[mt][2 * ks][0],     Sc[mt][2 * ks][1]);
                pa[mt][1] = packh2(Sc[mt][2 * ks][2],     Sc[mt][2 * ks][3]);
                pa[mt][2] = packh2(Sc[mt][2 * ks + 1][0], Sc[mt][2 * ks + 1][1]);
                pa[mt][3] = packh2(Sc[mt][2 * ks + 1][2], Sc[mt][2 * ks + 1][3]);
            }
            #pragma unroll
            for (int nt = 0; nt < 8; nt++) {
                unsigned bb[2];
                const float* vp = &Vsb[(ks * 16 + 2 * t) * VS_ST + nt * 8 + g];
                bb[0] = packh2(vp[0],          vp[VS_ST]);
                bb[1] = packh2(vp[8 * VS_ST],  vp[9 * VS_ST]);
                mma16(Oc[0][nt], pa[0], bb);
                mma16(Oc[1][nt], pa[1], bb);
            }
        }
        __syncthreads();   // before next tile's cp.async overwrites this buffer
    }

    // Epilogue: reduce row sums across the t-quad, normalize, write (B,L,D)
    #pragma unroll
    for (int mt = 0; mt < 2; mt++) {
        float sA = lpA[mt];
        sA += __shfl_xor_sync(0xffffffffu, sA, 1);
        sA += __shfl_xor_sync(0xffffffffu, sA, 2);
        float sB = lpB[mt];
        sB += __shfl_xor_sync(0xffffffffu, sB, 1);
        sB += __shfl_xor_sync(0xffffffffu, sB, 2);
        float iA = 1.f / sA, iB = 1.f / sB;

        int rowA = q0 + w * 32 + mt * 16 + g;
        size_t baseA = ((size_t)b * NL + rowA) * ND + h * NDK;
        size_t baseB = baseA + (size_t)8 * ND;
        #pragma unroll
        for (int nt = 0; nt < 8; nt++) {
            int cb = nt * 8 + 2 * t;
            *(float2*)&g_att[baseA + cb] =
                make_float2(Oc[mt][nt][0] * iA, Oc[mt][nt][1] * iA);
            *(float2*)&g_att[baseB + cb] =
                make_float2(Oc[mt][nt][2] * iB, Oc[mt][nt][3] * iB);
        }
    }
}

// ---------------------------------------------------------------------------
extern "C" void kernel_launch(void* const* d_in, const int* in_sizes, int n_in,
                              void* d_out, int out_size)
{
    (void)in_sizes; (void)n_in; (void)out_size;
    const float* x  = (const float*)d_in[0];
    const float* Wq = (const float*)d_in[1];
    const float* Wk = (const float*)d_in[2];
    const float* Wv = (const float*)d_in[3];
    const float* Wo = (const float*)d_in[4];
    const float* wf = (const float*)d_in[5];
    const float* wp = (const float*)d_in[6];
    float* out = (float*)d_out;

    float *Qp, *Kp, *Vp, *Ap;
    cudaGetSymbolAddress((void**)&Qp, g_Q);
    cudaGetSymbolAddress((void**)&Kp, g_K);
    cudaGetSymbolAddress((void**)&Vp, g_V);
    cudaGetSymbolAddress((void**)&Ap, g_att);

    cudaFuncSetAttribute(gemm_qkv, cudaFuncAttributeMaxDynamicSharedMemorySize, SMEM_GEMM4);
    cudaFuncSetAttribute(gemm_out, cudaFuncAttributeMaxDynamicSharedMemorySize, SMEM_GEMM2);
    cudaFuncSetAttribute(wave_attn_tc, cudaFuncAttributeMaxDynamicSharedMemorySize, SMEM_ATTN);

    dim3 ggrid(8, 32, 3);   // (N/64, M/256, qkv)
    gemm_qkv<<<ggrid, 256, SMEM_GEMM4>>>(x, Wq, Wk, Wv, Qp, Kp, Vp);

    wave_attn_tc<<<dim3(16, 32), 128, SMEM_ATTN>>>(wf, wp);

    gemm_out<<<dim3(8, 64), 256, SMEM_GEMM2>>>(Ap, Wo, out);
}

// round 14
// speedup vs baseline: 3.5361x; 1.3142x over previous
#include <cuda_runtime.h>
#include <cuda_fp16.h>
#include <math.h>

#define NB   4
#define NL   2048
#define ND   512
#define NH   8
#define NDK  64
#define NM   (NB*NL)   /* 8192 */

// fp16 scratch (static __device__ arrays — allocation-free per harness rules)
__device__ __half g_hx[NM*ND];      // x in fp16
__device__ __half g_hWq[ND*ND];
__device__ __half g_hWk[ND*ND];
__device__ __half g_hWv[ND*ND];
__device__ __half g_hWo[ND*ND];
__device__ __half g_hQ[NM*ND];      // (B,H,L,dk), pre-scaled by 0.125
__device__ __half g_hK[NM*ND];      // (B,H,L,dk)
__device__ __half g_hV[NM*ND];      // (B,H,L,dk)
__device__ __half g_hatt[NM*ND];    // (B,L,D)

// ---------------------------------------------------------------------------
// helpers
// ---------------------------------------------------------------------------
// pack two fp32 into f16x2 (lo = first arg). PTX: first src -> hi half.
__device__ __forceinline__ unsigned packh2(float lo, float hi) {
    unsigned r;
    asm("cvt.rn.f16x2.f32 %0, %1, %2;" : "=r"(r) : "f"(hi), "f"(lo));
    return r;
}
__device__ __forceinline__ unsigned ssa(const void* p) {
    return (unsigned)__cvta_generic_to_shared(p);
}
__device__ __forceinline__ void ldsm4(unsigned* r, unsigned a) {
    asm volatile("ldmatrix.sync.aligned.m8n8.x4.shared.b16 {%0,%1,%2,%3}, [%4];"
                 : "=r"(r[0]), "=r"(r[1]), "=r"(r[2]), "=r"(r[3]) : "r"(a));
}
__device__ __forceinline__ void ldsm4t(unsigned* r, unsigned a) {
    asm volatile("ldmatrix.sync.aligned.m8n8.x4.trans.shared.b16 {%0,%1,%2,%3}, [%4];"
                 : "=r"(r[0]), "=r"(r[1]), "=r"(r[2]), "=r"(r[3]) : "r"(a));
}
__device__ __forceinline__ void cpa16(__half* sptr, const __half* gptr) {
    asm volatile("cp.async.cg.shared.global [%0], [%1], 16;"
                 :: "r"(ssa(sptr)), "l"(gptr));
}
__device__ __forceinline__ void cpa_commit() {
    asm volatile("cp.async.commit_group;" ::: "memory");
}
__device__ __forceinline__ void cpa_wait1() {
    asm volatile("cp.async.wait_group 1;" ::: "memory");
}
__device__ __forceinline__ void cpa_wait0() {
    asm volatile("cp.async.wait_group 0;" ::: "memory");
}

// D(16x8) += A(16x16) * B(16x8), fp16 inputs, fp32 accumulate.
__device__ __forceinline__ void mma16(float* d, const unsigned* a, const unsigned* b) {
    asm volatile("mma.sync.aligned.m16n8k16.row.col.f32.f16.f16.f32 "
                 "{%0,%1,%2,%3}, {%4,%5,%6,%7}, {%8,%9}, {%0,%1,%2,%3};"
                 : "+f"(d[0]), "+f"(d[1]), "+f"(d[2]), "+f"(d[3])
                 : "r"(a[0]), "r"(a[1]), "r"(a[2]), "r"(a[3]),
                   "r"(b[0]), "r"(b[1]));
}

// ---------------------------------------------------------------------------
// fp32 -> fp16 conversion (one-time, vectorized by 4)
// ---------------------------------------------------------------------------
__global__ void to_fp16(const float* __restrict__ src, __half* __restrict__ dst, int n4)
{
    int i = blockIdx.x * blockDim.x + threadIdx.x;
    if (i < n4) {
        float4 v = ((const float4*)src)[i];
        uint2 o;
        o.x = packh2(v.x, v.y);
        o.y = packh2(v.z, v.w);
        ((uint2*)dst)[i] = o;
    }
}

// ---------------------------------------------------------------------------
// GEMM (fp16 in, ldmatrix fragments, cp.async double-buffered, K-chunk 64):
// Y = X @ W^T. X: (NM,512) fp16, W: (512,512) fp16 ([n][k] row-major).
// Block tile (MT*64)m x 64n, 8 warps in 4(m) x 2(n), warp tile (MT*16) x 32.
// Stride 72 halves = 144 B (odd multiple of 16 mod 128 -> ldmatrix
// phase-conflict-free; also 16B-aligned rows for cp.async).
// mode 0: fp32 Y[m*512+n]; mode 1: fp16 (B,H,L,dk) scatter (h=blockIdx.x),
// with `scale` folded in (0.125 for Q, 1 for K/V).
// ---------------------------------------------------------------------------
#define GST 72

template<int MT>
__device__ __forceinline__
void gemm_body(const __half* __restrict__ X, const __half* __restrict__ W,
               float* __restrict__ Yf, __half* __restrict__ Yh,
               int mode, float scale)
{
    constexpr int BM = MT * 64;
    extern __shared__ __half smh[];
    __half* Xs0 = smh;                       // 2 x BM*GST
    __half* Ws0 = smh + 2 * BM * GST;        // 2 x 64*GST

    const int tid  = threadIdx.x;
    const int w    = tid >> 5, lane = tid & 31;
    const int g    = lane >> 2, t = lane & 3;
    const int wm   = w & 3, wn = w >> 2;
    const int m0   = blockIdx.y * BM, n0 = blockIdx.x * 64;

    float acc[MT][4][4];
    #pragma unroll
    for (int mt = 0; mt < MT; mt++)
        #pragma unroll
        for (int nt = 0; nt < 4; nt++)
            #pragma unroll
            for (int i = 0; i < 4; i++) acc[mt][nt][i] = 0.f;

    // async stage of one K64 chunk into buffer `buf`
    auto stage = [&](int k0, int buf) {
        __half* Xs = Xs0 + buf * BM * GST;
        __half* Ws = Ws0 + buf * 64 * GST;
        #pragma unroll
        for (int i = 0; i < MT * 2; i++) {     // BM rows x 8 chunks / 256 thr
            int idx = tid + 256 * i;
            int r = idx >> 3, c = (idx & 7) * 8;
            cpa16(&Xs[r * GST + c], &X[(size_t)(m0 + r) * 512 + k0 + c]);
        }
        #pragma unroll
        for (int i = 0; i < 2; i++) {          // 64 rows x 8 chunks / 256 thr
            int idx = tid + 256 * i;
            int r = idx >> 3, c = (idx & 7) * 8;
            cpa16(&Ws[r * GST + c], &W[(size_t)(n0 + r) * 512 + k0 + c]);
        }
        cpa_commit();
    };

    const int l15 = lane & 15, lhi = (lane >> 4) & 1;   // A-load lanes
    const int l8  = lane & 7,  seg = lane >> 3;         // B-load lanes

    stage(0, 0);
    for (int kc = 0; kc < 8; kc++) {
        if (kc + 1 < 8) { stage((kc + 1) * 64, (kc + 1) & 1); cpa_wait1(); }
        else            { cpa_wait0(); }
        __syncthreads();

        const __half* Xs = Xs0 + (kc & 1) * BM * GST;
        const __half* Ws = Ws0 + (kc & 1) * 64 * GST;

        #pragma unroll
        for (int ks = 0; ks < 4; ks++) {       // four k16 steps per K64 chunk
            unsigned a[MT][4], bb[4][2];
            #pragma unroll
            for (int mt = 0; mt < MT; mt++) {
                // A 16x16: lanes 0-15 rows, 16-31 same rows col+8
                unsigned ad = ssa(&Xs[(wm * (MT * 16) + mt * 16 + l15) * GST
                                      + ks * 16 + lhi * 8]);
                ldsm4(a[mt], ad);
            }
            #pragma unroll
            for (int ntp = 0; ntp < 4; ntp += 2) {
                // B from [n][k]: seg0=(ntp,klo) seg1=(ntp,khi) seg2/3=ntp+1
                unsigned bd = ssa(&Ws[(wn * 32 + (ntp + (seg >> 1)) * 8 + l8) * GST
                                      + ks * 16 + (seg & 1) * 8]);
                unsigned r4[4];
                ldsm4(r4, bd);
                bb[ntp][0] = r4[0]; bb[ntp][1] = r4[1];
                bb[ntp + 1][0] = r4[2]; bb[ntp + 1][1] = r4[3];
            }
            #pragma unroll
            for (int mt = 0; mt < MT; mt++)
                #pragma unroll
                for (int nt = 0; nt < 4; nt++)
                    mma16(acc[mt][nt], a[mt], bb[nt]);
        }
        __syncthreads();
    }

    // Epilogue
    #pragma unroll
    for (int mt = 0; mt < MT; mt++) {
        int row = m0 + wm * (MT * 16) + mt * 16 + g;
        #pragma unroll
        for (int nt = 0; nt < 4; nt++) {
            int off = wn * 32 + nt * 8 + 2 * t;      // 0..63 within n-block
            if (mode == 0) {
                float* p = &Yf[(size_t)row * 512 + n0 + off];
                *(float2*)p = make_float2(acc[mt][nt][0], acc[mt][nt][1]);
                *(float2*)(p + (size_t)8 * 512) =
                    make_float2(acc[mt][nt][2], acc[mt][nt][3]);
            } else {
                int b = row >> 11, l = row & 2047, h = blockIdx.x;
                size_t base = ((size_t)((b * 8 + h) * 2048 + l)) * 64 + off;
                *(unsigned*)&Yh[base] =
                    packh2(acc[mt][nt][0] * scale, acc[mt][nt][1] * scale);
                *(unsigned*)&Yh[base + (size_t)8 * 64] =
                    packh2(acc[mt][nt][2] * scale, acc[mt][nt][3] * scale);
            }
        }
    }
}

#define SMEM_GEMM4 ((2 * 256 * GST + 2 * 64 * GST) * 2)   /* 92160 B */
#define SMEM_GEMM2 ((2 * 128 * GST + 2 * 64 * GST) * 2)   /* 55296 B */

// Fused Q/K/V projection: gridDim.z = 3 selects weight + destination.
__global__ __launch_bounds__(256)
void gemm_qkv()
{
    const __half* W = (blockIdx.z == 0) ? g_hWq : (blockIdx.z == 1) ? g_hWk : g_hWv;
    __half*       Y = (blockIdx.z == 0) ? g_hQ  : (blockIdx.z == 1) ? g_hK  : g_hV;
    float scale = (blockIdx.z == 0) ? 0.125f : 1.f;
    gemm_body<4>(g_hx, W, nullptr, Y, 1, scale);
}

__global__ __launch_bounds__(256)
void gemm_out(float* __restrict__ out)
{
    gemm_body<2>(g_hatt, g_hWo, out, nullptr, 0, 1.f);
}

// ---------------------------------------------------------------------------
// Wave attention (fp16 + ldmatrix): 128 q-rows per block, 4 warps (32 rows
// each as 2 m-tiles), stream 64-key tiles, cp.async double-buffered fp16 K/V.
// FIXED-MAX softmax (scores bounded: p = exp(s), end normalization).
// K fragments: ldmatrix x4 non-trans from [key][dk]; V: ldmatrix x4 .trans
// from [key][dk]. P: register packs of S accumulators (no shuffles/smem).
// Smem: Ks[2][64*72] + Vs[2][64*72] halves + wave[2048] f32 = 45056 B.
// ---------------------------------------------------------------------------
#define KS_ST 72
#define SMEM_ATTN (4 * 64 * KS_ST * 2 + 2048 * 4)

__global__ __launch_bounds__(128, 2)
void wave_attn_tc(const float* __restrict__ wfreq, const float* __restrict__ wphase)
{
    extern __shared__ __half smh[];
    __half* Ks0 = smh;
    __half* Vs0 = smh + 2 * 64 * KS_ST;
    float*  Wv  = (float*)(smh + 4 * 64 * KS_ST);

    const int tid = threadIdx.x;
    const int w   = tid >> 5, lane = tid & 31;
    const int g   = lane >> 2, t = lane & 3;
    const int bh  = blockIdx.y, b = bh >> 3, h = bh & 7;
    const int q0  = blockIdx.x * 128;

    const __half* Qh = g_hQ + ((size_t)bh * NL + q0) * NDK;
    const __half* Kh = g_hK + (size_t)bh * NL * NDK;
    const __half* Vh = g_hV + (size_t)bh * NL * NDK;

    // async stage of fp16 K/V tile kt into buffer `buf`
    auto stage_kv = [&](int kt, int buf) {
        __half* Ksb = Ks0 + buf * 64 * KS_ST;
        __half* Vsb = Vs0 + buf * 64 * KS_ST;
        #pragma unroll
        for (int i = 0; i < 4; i++) {
            int idx = tid + 128 * i;           // 0..511
            int r = idx >> 3, c = (idx & 7) * 8;
            cpa16(&Ksb[r * KS_ST + c], &Kh[(size_t)(kt * 64 + r) * 64 + c]);
            cpa16(&Vsb[r * KS_ST + c], &Vh[(size_t)(kt * 64 + r) * 64 + c]);
        }
        cpa_commit();
    };

    stage_kv(0, 0);   // tile 0 in flight while we do wave table + Q fragments

    // Wave table (once per block)
    {
        const float f = wfreq[h], ph = wphase[h];
        const float TWO_PI = 6.28318530717958647692f;
        for (int j = tid; j < NL; j += 128)
            Wv[j] = cosf(TWO_PI * f * (float)j + ph);
    }

    // Q A-fragments straight from gmem (already fp16, pre-scaled)
    unsigned Qa[2][4][4];
    #pragma unroll
    for (int mt = 0; mt < 2; mt++)
        #pragma unroll
        for (int ks = 0; ks < 4; ks++) {
            const __half* qp = &Qh[(w * 32 + mt * 16 + g) * 64 + ks * 16 + 2 * t];
            Qa[mt][ks][0] = *(const unsigned*)&qp[0];
            Qa[mt][ks][1] = *(const unsigned*)&qp[512];
            Qa[mt][ks][2] = *(const unsigned*)&qp[8];
            Qa[mt][ks][3] = *(const unsigned*)&qp[520];
        }

    float Oc[2][8][4];
    #pragma unroll
    for (int mt = 0; mt < 2; mt++)
        #pragma unroll
        for (int nt = 0; nt < 8; nt++)
            #pragma unroll
            for (int i = 0; i < 4; i++) Oc[mt][nt][i] = 0.f;
    float lpA[2] = {0.f, 0.f}, lpB[2] = {0.f, 0.f};   // per-thread row sums

    const int l8 = lane & 7, seg = lane >> 3;

    for (int kt = 0; kt < 32; kt++) {
        if (kt + 1 < 32) { stage_kv(kt + 1, (kt + 1) & 1); cpa_wait1(); }
        else             { cpa_wait0(); }
        __syncthreads();

        const __half* Ksb = Ks0 + (kt & 1) * 64 * KS_ST;
        const __half* Vsb = Vs0 + (kt & 1) * 64 * KS_ST;

        // S = Q @ K^T : K fragments via ldmatrix x4 (2 n-tiles per load)
        float Sc[2][8][4];
        #pragma unroll
        for (int mt = 0; mt < 2; mt++)
            #pragma unroll
            for (int nt = 0; nt < 8; nt++)
                #pragma unroll
                for (int i = 0; i < 4; i++) Sc[mt][nt][i] = 0.f;
        #pragma unroll
        for (int ks = 0; ks < 4; ks++) {
            #pragma unroll
            for (int ntp = 0; ntp < 8; ntp += 2) {
                unsigned r4[4];
                unsigned kd = ssa(&Ksb[((ntp + (seg >> 1)) * 8 + l8) * KS_ST
                                       + ks * 16 + (seg & 1) * 8]);
                ldsm4(r4, kd);
                mma16(Sc[0][ntp],     Qa[0][ks], r4);
                mma16(Sc[1][ntp],     Qa[1][ks], r4);
                mma16(Sc[0][ntp + 1], Qa[0][ks], r4 + 2);
                mma16(Sc[1][ntp + 1], Qa[1][ks], r4 + 2);
            }
        }

        // Wave modulation + fixed-max exp; accumulate per-thread row sums
        #pragma unroll
        for (int mt = 0; mt < 2; mt++) {
            #pragma unroll
            for (int nt = 0; nt < 8; nt++) {
                int col = kt * 64 + nt * 8 + 2 * t;
                float w0 = Wv[col], w1 = Wv[col + 1];
                float p0 = __expf(Sc[mt][nt][0] * w0);
                float p1 = __expf(Sc[mt][nt][1] * w1);
                float p2 = __expf(Sc[mt][nt][2] * w0);
                float p3 = __expf(Sc[mt][nt][3] * w1);
                lpA[mt] += p0 + p1;
                lpB[mt] += p2 + p3;
                Sc[mt][nt][0] = p0; Sc[mt][nt][1] = p1;
                Sc[mt][nt][2] = p2; Sc[mt][nt][3] = p3;
            }
        }

        // O += P @ V : P A-fragments are packs of the S accumulators;
        // V B-fragments via ldmatrix x4 .trans from [k][n] layout.
        #pragma unroll
        for (int ks = 0; ks < 4; ks++) {
            unsigned pa[2][4];
            #pragma unroll
            for (int mt = 0; mt < 2; mt++) {
                pa[mt][0] = packh2(Sc[mt][2 * ks][0],     Sc[mt][2 * ks][1]);
                pa[mt][1] = packh2(Sc[mt][2 * ks][2],     Sc[mt][2 * ks][3]);
                pa[mt][2] = packh2(Sc[mt][2 * ks + 1][0], Sc[mt][2 * ks + 1][1]);
                pa[mt][3] = packh2(Sc[mt][2 * ks + 1][2], Sc[mt][2 * ks + 1][3]);
            }
            #pragma unroll
            for (int ntp = 0; ntp < 8; ntp += 2) {
                unsigned r4[4];
                unsigned vd = ssa(&Vsb[(ks * 16 + (seg & 1) * 8 + l8) * KS_ST
                                       + (ntp + (seg >> 1)) * 8]);
                ldsm4t(r4, vd);
                mma16(Oc[0][ntp],     pa[0], r4);
                mma16(Oc[1][ntp],     pa[1], r4);
                mma16(Oc[0][ntp + 1], pa[0], r4 + 2);
                mma16(Oc[1][ntp + 1], pa[1], r4 + 2);
            }
        }
        __syncthreads();   // before next tile's cp.async overwrites this buffer
    }

    // Epilogue: reduce row sums across t-quad, normalize, write fp16 (B,L,D)
    #pragma unroll
    for (int mt = 0; mt < 2; mt++) {
        float sA = lpA[mt];
        sA += __shfl_xor_sync(0xffffffffu, sA, 1);
        sA += __shfl_xor_sync(0xffffffffu, sA, 2);
        float sB = lpB[mt];
        sB += __shfl_xor_sync(0xffffffffu, sB, 1);
        sB += __shfl_xor_sync(0xffffffffu, sB, 2);
        float iA = 1.f / sA, iB = 1.f / sB;

        int rowA = q0 + w * 32 + mt * 16 + g;
        size_t baseA = ((size_t)b * NL + rowA) * ND + h * NDK;
        size_t baseB = baseA + (size_t)8 * ND;
        #pragma unroll
        for (int nt = 0; nt < 8; nt++) {
            int cb = nt * 8 + 2 * t;
            *(unsigned*)&g_hatt[baseA + cb] =
                packh2(Oc[mt][nt][0] * iA, Oc[mt][nt][1] * iA);
            *(unsigned*)&g_hatt[baseB + cb] =
                packh2(Oc[mt][nt][2] * iB, Oc[mt][nt][3] * iB);
        }
    }
}

// ---------------------------------------------------------------------------
extern "C" void kernel_launch(void* const* d_in, const int* in_sizes, int n_in,
                              void* d_out, int out_size)
{
    (void)in_sizes; (void)n_in; (void)out_size;
    const float* x  = (const float*)d_in[0];
    const float* Wq = (const float*)d_in[1];
    const float* Wk = (const float*)d_in[2];
    const float* Wv = (const float*)d_in[3];
    const float* Wo = (const float*)d_in[4];
    const float* wf = (const float*)d_in[5];
    const float* wp = (const float*)d_in[6];
    float* out = (float*)d_out;

    __half *hx, *hWq, *hWk, *hWv, *hWo;
    cudaGetSymbolAddress((void**)&hx,  g_hx);
    cudaGetSymbolAddress((void**)&hWq, g_hWq);
    cudaGetSymbolAddress((void**)&hWk, g_hWk);
    cudaGetSymbolAddress((void**)&hWv, g_hWv);
    cudaGetSymbolAddress((void**)&hWo, g_hWo);

    cudaFuncSetAttribute(gemm_qkv, cudaFuncAttributeMaxDynamicSharedMemorySize, SMEM_GEMM4);
    cudaFuncSetAttribute(gemm_out, cudaFuncAttributeMaxDynamicSharedMemorySize, SMEM_GEMM2);
    cudaFuncSetAttribute(wave_attn_tc, cudaFuncAttributeMaxDynamicSharedMemorySize, SMEM_ATTN);

    // one-time fp32 -> fp16 conversion of inputs
    to_fp16<<<(NM * ND / 4 + 255) / 256, 256>>>(x,  hx,  NM * ND / 4);
    to_fp16<<<(ND * ND / 4 + 255) / 256, 256>>>(Wq, hWq, ND * ND / 4);
    to_fp16<<<(ND * ND / 4 + 255) / 256, 256>>>(Wk, hWk, ND * ND / 4);
    to_fp16<<<(ND * ND / 4 + 255) / 256, 256>>>(Wv, hWv, ND * ND / 4);
    to_fp16<<<(ND * ND / 4 + 255) / 256, 256>>>(Wo, hWo, ND * ND / 4);

    gemm_qkv<<<dim3(8, 32, 3), 256, SMEM_GEMM4>>>();

    wave_attn_tc<<<dim3(16, 32), 128, SMEM_ATTN>>>(wf, wp);

    gemm_out<<<dim3(8, 64), 256, SMEM_GEMM2>>>(out);
}

// round 16
// speedup vs baseline: 3.7025x; 1.0471x over previous
#include <cuda_runtime.h>
#include <cuda_fp16.h>
#include <math.h>

#define NB   4
#define NL   2048
#define ND   512
#define NH   8
#define NDK  64
#define NM   (NB*NL)   /* 8192 */

// fp16 scratch (static __device__ arrays — allocation-free per harness rules)
__device__ __half g_hx[NM*ND];      // x in fp16
__device__ __half g_hWq[ND*ND];
__device__ __half g_hWk[ND*ND];
__device__ __half g_hWv[ND*ND];
__device__ __half g_hWo[ND*ND];
__device__ __half g_hQ[NM*ND];      // (B,H,L,dk), pre-scaled by 0.125
__device__ __half g_hK[NM*ND];      // (B,H,L,dk)
__device__ __half g_hV[NM*ND];      // (B,H,L,dk)
__device__ __half g_hatt[NM*ND];    // (B,L,D)

// ---------------------------------------------------------------------------
// helpers
// ---------------------------------------------------------------------------
// pack two fp32 into f16x2 (lo = first arg). PTX: first src -> hi half.
__device__ __forceinline__ unsigned packh2(float lo, float hi) {
    unsigned r;
    asm("cvt.rn.f16x2.f32 %0, %1, %2;" : "=r"(r) : "f"(hi), "f"(lo));
    return r;
}
__device__ __forceinline__ unsigned ssa(const void* p) {
    return (unsigned)__cvta_generic_to_shared(p);
}
__device__ __forceinline__ void ldsm4(unsigned* r, unsigned a) {
    asm volatile("ldmatrix.sync.aligned.m8n8.x4.shared.b16 {%0,%1,%2,%3}, [%4];"
                 : "=r"(r[0]), "=r"(r[1]), "=r"(r[2]), "=r"(r[3]) : "r"(a));
}
__device__ __forceinline__ void ldsm4t(unsigned* r, unsigned a) {
    asm volatile("ldmatrix.sync.aligned.m8n8.x4.trans.shared.b16 {%0,%1,%2,%3}, [%4];"
                 : "=r"(r[0]), "=r"(r[1]), "=r"(r[2]), "=r"(r[3]) : "r"(a));
}
__device__ __forceinline__ void cpa16(__half* sptr, const __half* gptr) {
    asm volatile("cp.async.cg.shared.global [%0], [%1], 16;"
                 :: "r"(ssa(sptr)), "l"(gptr));
}
__device__ __forceinline__ void cpa_commit() {
    asm volatile("cp.async.commit_group;" ::: "memory");
}
__device__ __forceinline__ void cpa_wait1() {
    asm volatile("cp.async.wait_group 1;" ::: "memory");
}
__device__ __forceinline__ void cpa_wait0() {
    asm volatile("cp.async.wait_group 0;" ::: "memory");
}

// D(16x8) += A(16x16) * B(16x8), fp16 inputs, fp32 accumulate.
__device__ __forceinline__ void mma16(float* d, const unsigned* a, const unsigned* b) {
    asm volatile("mma.sync.aligned.m16n8k16.row.col.f32.f16.f16.f32 "
                 "{%0,%1,%2,%3}, {%4,%5,%6,%7}, {%8,%9}, {%0,%1,%2,%3};"
                 : "+f"(d[0]), "+f"(d[1]), "+f"(d[2]), "+f"(d[3])
                 : "r"(a[0]), "r"(a[1]), "r"(a[2]), "r"(a[3]),
                   "r"(b[0]), "r"(b[1]));
}

// ---------------------------------------------------------------------------
// fp32 -> fp16 conversion: ONE launch covering x + all 4 weights.
// Segment 0: x (1048576 float4). Segments 1-4: weights (65536 float4 each).
// ---------------------------------------------------------------------------
#define CV_X4  (NM * ND / 4)       /* 1048576 */
#define CV_W4  (ND * ND / 4)       /*   65536 */
#define CV_TOT (CV_X4 + 4 * CV_W4) /* 1310720 */

__global__ void to_fp16_all(const float* __restrict__ x,
                            const float* __restrict__ Wq, const float* __restrict__ Wk,
                            const float* __restrict__ Wv, const float* __restrict__ Wo)
{
    int i = blockIdx.x * blockDim.x + threadIdx.x;
    if (i >= CV_TOT) return;
    const float* src;
    __half* dst;
    int off;
    if (i < CV_X4) {
        src = x; dst = g_hx; off = i;
    } else {
        int j = i - CV_X4;
        int seg = j >> 16;          // 65536 float4 per weight
        off = j & 65535;
        src = (seg == 0) ? Wq : (seg == 1) ? Wk : (seg == 2) ? Wv : Wo;
        dst = (seg == 0) ? g_hWq : (seg == 1) ? g_hWk : (seg == 2) ? g_hWv : g_hWo;
    }
    float4 v = ((const float4*)src)[off];
    uint2 o;
    o.x = packh2(v.x, v.y);
    o.y = packh2(v.z, v.w);
    ((uint2*)dst)[off] = o;
}

// ---------------------------------------------------------------------------
// GEMM (fp16 in, ldmatrix fragments, cp.async double-buffered, K-chunk 64):
// Y = X @ W^T. X: (NM,512) fp16, W: (512,512) fp16 ([n][k] row-major).
// Block tile (MT*64)m x 64n, 8 warps in 4(m) x 2(n), warp tile (MT*16) x 32.
// Stride 72 halves = 144 B (odd multiple of 16 mod 128 -> ldmatrix
// phase-conflict-free; also 16B-aligned rows for cp.async).
// __launch_bounds__(256,2): reg cap 128 (same as measured allocation) ->
// 2 blocks/SM, 4 warps/SMSP for latency hiding.
// mode 0: fp32 Y[m*512+n]; mode 1: fp16 (B,H,L,dk) scatter (h=blockIdx.x),
// with `scale` folded in (0.125 for Q, 1 for K/V).
// ---------------------------------------------------------------------------
#define GST 72

template<int MT>
__device__ __forceinline__
void gemm_body(const __half* __restrict__ X, const __half* __restrict__ W,
               float* __restrict__ Yf, __half* __restrict__ Yh,
               int mode, float scale)
{
    constexpr int BM = MT * 64;
    extern __shared__ __half smh[];
    __half* Xs0 = smh;                       // 2 x BM*GST
    __half* Ws0 = smh + 2 * BM * GST;        // 2 x 64*GST

    const int tid  = threadIdx.x;
    const int w    = tid >> 5, lane = tid & 31;
    const int g    = lane >> 2, t = lane & 3;
    const int wm   = w & 3, wn = w >> 2;
    const int m0   = blockIdx.y * BM, n0 = blockIdx.x * 64;

    float acc[MT][4][4];
    #pragma unroll
    for (int mt = 0; mt < MT; mt++)
        #pragma unroll
        for (int nt = 0; nt < 4; nt++)
            #pragma unroll
            for (int i = 0; i < 4; i++) acc[mt][nt][i] = 0.f;

    // async stage of one K64 chunk into buffer `buf`
    auto stage = [&](int k0, int buf) {
        __half* Xs = Xs0 + buf * BM * GST;
        __half* Ws = Ws0 + buf * 64 * GST;
        #pragma unroll
        for (int i = 0; i < MT * 2; i++) {     // BM rows x 8 chunks / 256 thr
            int idx = tid + 256 * i;
            int r = idx >> 3, c = (idx & 7) * 8;
            cpa16(&Xs[r * GST + c], &X[(size_t)(m0 + r) * 512 + k0 + c]);
        }
        #pragma unroll
        for (int i = 0; i < 2; i++) {          // 64 rows x 8 chunks / 256 thr
            int idx = tid + 256 * i;
            int r = idx >> 3, c = (idx & 7) * 8;
            cpa16(&Ws[r * GST + c], &W[(size_t)(n0 + r) * 512 + k0 + c]);
        }
        cpa_commit();
    };

    const int l15 = lane & 15, lhi = (lane >> 4) & 1;   // A-load lanes
    const int l8  = lane & 7,  seg = lane >> 3;         // B-load lanes

    stage(0, 0);
    for (int kc = 0; kc < 8; kc++) {
        if (kc + 1 < 8) { stage((kc + 1) * 64, (kc + 1) & 1); cpa_wait1(); }
        else            { cpa_wait0(); }
        __syncthreads();

        const __half* Xs = Xs0 + (kc & 1) * BM * GST;
        const __half* Ws = Ws0 + (kc & 1) * 64 * GST;

        #pragma unroll
        for (int ks = 0; ks < 4; ks++) {       // four k16 steps per K64 chunk
            unsigned a[MT][4], bb[4][2];
            #pragma unroll
            for (int mt = 0; mt < MT; mt++) {
                // A 16x16: lanes 0-15 rows, 16-31 same rows col+8
                unsigned ad = ssa(&Xs[(wm * (MT * 16) + mt * 16 + l15) * GST
                                      + ks * 16 + lhi * 8]);
                ldsm4(a[mt], ad);
            }
            #pragma unroll
            for (int ntp = 0; ntp < 4; ntp += 2) {
                // B from [n][k]: seg0=(ntp,klo) seg1=(ntp,khi) seg2/3=ntp+1
                unsigned bd = ssa(&Ws[(wn * 32 + (ntp + (seg >> 1)) * 8 + l8) * GST
                                      + ks * 16 + (seg & 1) * 8]);
                unsigned r4[4];
                ldsm4(r4, bd);
                bb[ntp][0] = r4[0]; bb[ntp][1] = r4[1];
                bb[ntp + 1][0] = r4[2]; bb[ntp + 1][1] = r4[3];
            }
            #pragma unroll
            for (int mt = 0; mt < MT; mt++)
                #pragma unroll
                for (int nt = 0; nt < 4; nt++)
                    mma16(acc[mt][nt], a[mt], bb[nt]);
        }
        __syncthreads();
    }

    // Epilogue
    #pragma unroll
    for (int mt = 0; mt < MT; mt++) {
        int row = m0 + wm * (MT * 16) + mt * 16 + g;
        #pragma unroll
        for (int nt = 0; nt < 4; nt++) {
            int off = wn * 32 + nt * 8 + 2 * t;      // 0..63 within n-block
            if (mode == 0) {
                float* p = &Yf[(size_t)row * 512 + n0 + off];
                *(float2*)p = make_float2(acc[mt][nt][0], acc[mt][nt][1]);
                *(float2*)(p + (size_t)8 * 512) =
                    make_float2(acc[mt][nt][2], acc[mt][nt][3]);
            } else {
                int b = row >> 11, l = row & 2047, h = blockIdx.x;
                size_t base = ((size_t)((b * 8 + h) * 2048 + l)) * 64 + off;
                *(unsigned*)&Yh[base] =
                    packh2(acc[mt][nt][0] * scale, acc[mt][nt][1] * scale);
                *(unsigned*)&Yh[base + (size_t)8 * 64] =
                    packh2(acc[mt][nt][2] * scale, acc[mt][nt][3] * scale);
            }
        }
    }
}

#define SMEM_GEMM4 ((2 * 256 * GST + 2 * 64 * GST) * 2)   /* 92160 B */
#define SMEM_GEMM2 ((2 * 128 * GST + 2 * 64 * GST) * 2)   /* 55296 B */

// Fused Q/K/V projection: gridDim.z = 3 selects weight + destination.
__global__ __launch_bounds__(256, 2)
void gemm_qkv()
{
    const __half* W = (blockIdx.z == 0) ? g_hWq : (blockIdx.z == 1) ? g_hWk : g_hWv;
    __half*       Y = (blockIdx.z == 0) ? g_hQ  : (blockIdx.z == 1) ? g_hK  : g_hV;
    float scale = (blockIdx.z == 0) ? 0.125f : 1.f;
    gemm_body<4>(g_hx, W, nullptr, Y, 1, scale);
}

__global__ __launch_bounds__(256, 2)
void gemm_out(float* __restrict__ out)
{
    gemm_body<2>(g_hatt, g_hWo, out, nullptr, 0, 1.f);
}

// ---------------------------------------------------------------------------
// Wave attention (fp16 + ldmatrix): 128 q-rows per block, 4 warps (32 rows
// each as 2 m-tiles), stream 64-key tiles, cp.async double-buffered fp16 K/V.
// FIXED-MAX softmax (scores bounded: p = exp(s), end normalization).
// K fragments: ldmatrix x4 non-trans from [key][dk]; V: ldmatrix x4 .trans
// from [key][dk]. P: register packs of S accumulators (no shuffles/smem).
// Smem: Ks[2][64*72] + Vs[2][64*72] halves + wave[2048] f32 = 45056 B.
// ---------------------------------------------------------------------------
#define KS_ST 72
#define SMEM_ATTN (4 * 64 * KS_ST * 2 + 2048 * 4)

__global__ __launch_bounds__(128, 2)
void wave_attn_tc(const float* __restrict__ wfreq, const float* __restrict__ wphase)
{
    extern __shared__ __half smh[];
    __half* Ks0 = smh;
    __half* Vs0 = smh + 2 * 64 * KS_ST;
    float*  Wv  = (float*)(smh + 4 * 64 * KS_ST);

    const int tid = threadIdx.x;
    const int w   = tid >> 5, lane = tid & 31;
    const int g   = lane >> 2, t = lane & 3;
    const int bh  = blockIdx.y, b = bh >> 3, h = bh & 7;
    const int q0  = blockIdx.x * 128;

    const __half* Qh = g_hQ + ((size_t)bh * NL + q0) * NDK;
    const __half* Kh = g_hK + (size_t)bh * NL * NDK;
    const __half* Vh = g_hV + (size_t)bh * NL * NDK;

    // async stage of fp16 K/V tile kt into buffer `buf`
    auto stage_kv = [&](int kt, int buf) {
        __half* Ksb = Ks0 + buf * 64 * KS_ST;
        __half* Vsb = Vs0 + buf * 64 * KS_ST;
        #pragma unroll
        for (int i = 0; i < 4; i++) {
            int idx = tid + 128 * i;           // 0..511
            int r = idx >> 3, c = (idx & 7) * 8;
            cpa16(&Ksb[r * KS_ST + c], &Kh[(size_t)(kt * 64 + r) * 64 + c]);
            cpa16(&Vsb[r * KS_ST + c], &Vh[(size_t)(kt * 64 + r) * 64 + c]);
        }
        cpa_commit();
    };

    stage_kv(0, 0);   // tile 0 in flight while we do wave table + Q fragments

    // Wave table (once per block)
    {
        const float f = wfreq[h], ph = wphase[h];
        const float TWO_PI = 6.28318530717958647692f;
        for (int j = tid; j < NL; j += 128)
            Wv[j] = cosf(TWO_PI * f * (float)j + ph);
    }

    // Q A-fragments straight from gmem (already fp16, pre-scaled)
    unsigned Qa[2][4][4];
    #pragma unroll
    for (int mt = 0; mt < 2; mt++)
        #pragma unroll
        for (int ks = 0; ks < 4; ks++) {
            const __half* qp = &Qh[(w * 32 + mt * 16 + g) * 64 + ks * 16 + 2 * t];
            Qa[mt][ks][0] = *(const unsigned*)&qp[0];
            Qa[mt][ks][1] = *(const unsigned*)&qp[512];
            Qa[mt][ks][2] = *(const unsigned*)&qp[8];
            Qa[mt][ks][3] = *(const unsigned*)&qp[520];
        }

    float Oc[2][8][4];
    #pragma unroll
    for (int mt = 0; mt < 2; mt++)
        #pragma unroll
        for (int nt = 0; nt < 8; nt++)
            #pragma unroll
            for (int i = 0; i < 4; i++) Oc[mt][nt][i] = 0.f;
    float lpA[2] = {0.f, 0.f}, lpB[2] = {0.f, 0.f};   // per-thread row sums

    const int l8 = lane & 7, seg = lane >> 3;

    for (int kt = 0; kt < 32; kt++) {
        if (kt + 1 < 32) { stage_kv(kt + 1, (kt + 1) & 1); cpa_wait1(); }
        else             { cpa_wait0(); }
        __syncthreads();

        const __half* Ksb = Ks0 + (kt & 1) * 64 * KS_ST;
        const __half* Vsb = Vs0 + (kt & 1) * 64 * KS_ST;

        // S = Q @ K^T : K fragments via ldmatrix x4 (2 n-tiles per load)
        float Sc[2][8][4];
        #pragma unroll
        for (int mt = 0; mt < 2; mt++)
            #pragma unroll
            for (int nt = 0; nt < 8; nt++)
                #pragma unroll
                for (int i = 0; i < 4; i++) Sc[mt][nt][i] = 0.f;
        #pragma unroll
        for (int ks = 0; ks < 4; ks++) {
            #pragma unroll
            for (int ntp = 0; ntp < 8; ntp += 2) {
                unsigned r4[4];
                unsigned kd = ssa(&Ksb[((ntp + (seg >> 1)) * 8 + l8) * KS_ST
                                       + ks * 16 + (seg & 1) * 8]);
                ldsm4(r4, kd);
                mma16(Sc[0][ntp],     Qa[0][ks], r4);
                mma16(Sc[1][ntp],     Qa[1][ks], r4);
                mma16(Sc[0][ntp + 1], Qa[0][ks], r4 + 2);
                mma16(Sc[1][ntp + 1], Qa[1][ks], r4 + 2);
            }
        }

        // Wave modulation + fixed-max exp; accumulate per-thread row sums
        #pragma unroll
        for (int mt = 0; mt < 2; mt++) {
            #pragma unroll
            for (int nt = 0; nt < 8; nt++) {
                int col = kt * 64 + nt * 8 + 2 * t;
                float w0 = Wv[col], w1 = Wv[col + 1];
                float p0 = __expf(Sc[mt][nt][0] * w0);
                float p1 = __expf(Sc[mt][nt][1] * w1);
                float p2 = __expf(Sc[mt][nt][2] * w0);
                float p3 = __expf(Sc[mt][nt][3] * w1);
                lpA[mt] += p0 + p1;
                lpB[mt] += p2 + p3;
                Sc[mt][nt][0] = p0; Sc[mt][nt][1] = p1;
                Sc[mt][nt][2] = p2; Sc[mt][nt][3] = p3;
            }
        }

        // O += P @ V : P A-fragments are packs of the S accumulators;
        // V B-fragments via ldmatrix x4 .trans from [k][n] layout.
        #pragma unroll
        for (int ks = 0; ks < 4; ks++) {
            unsigned pa[2][4];
            #pragma unroll
            for (int mt = 0; mt < 2; mt++) {
                pa[mt][0] = packh2(Sc[mt][2 * ks][0],     Sc[mt][2 * ks][1]);
                pa[mt][1] = packh2(Sc[mt][2 * ks][2],     Sc[mt][2 * ks][3]);
                pa[mt][2] = packh2(Sc[mt][2 * ks + 1][0], Sc[mt][2 * ks + 1][1]);
                pa[mt][3] = packh2(Sc[mt][2 * ks + 1][2], Sc[mt][2 * ks + 1][3]);
            }
            #pragma unroll
            for (int ntp = 0; ntp < 8; ntp += 2) {
                unsigned r4[4];
                unsigned vd = ssa(&Vsb[(ks * 16 + (seg & 1) * 8 + l8) * KS_ST
                                       + (ntp + (seg >> 1)) * 8]);
                ldsm4t(r4, vd);
                mma16(Oc[0][ntp],     pa[0], r4);
                mma16(Oc[1][ntp],     pa[1], r4);
                mma16(Oc[0][ntp + 1], pa[0], r4 + 2);
                mma16(Oc[1][ntp + 1], pa[1], r4 + 2);
            }
        }
        __syncthreads();   // before next tile's cp.async overwrites this buffer
    }

    // Epilogue: reduce row sums across t-quad, normalize, write fp16 (B,L,D)
    #pragma unroll
    for (int mt = 0; mt < 2; mt++) {
        float sA = lpA[mt];
        sA += __shfl_xor_sync(0xffffffffu, sA, 1);
        sA += __shfl_xor_sync(0xffffffffu, sA, 2);
        float sB = lpB[mt];
        sB += __shfl_xor_sync(0xffffffffu, sB, 1);
        sB += __shfl_xor_sync(0xffffffffu, sB, 2);
        float iA = 1.f / sA, iB = 1.f / sB;

        int rowA = q0 + w * 32 + mt * 16 + g;
        size_t baseA = ((size_t)b * NL + rowA) * ND + h * NDK;
        size_t baseB = baseA + (size_t)8 * ND;
        #pragma unroll
        for (int nt = 0; nt < 8; nt++) {
            int cb = nt * 8 + 2 * t;
            *(unsigned*)&g_hatt[baseA + cb] =
                packh2(Oc[mt][nt][0] * iA, Oc[mt][nt][1] * iA);
            *(unsigned*)&g_hatt[baseB + cb] =
                packh2(Oc[mt][nt][2] * iB, Oc[mt][nt][3] * iB);
        }
    }
}

// ---------------------------------------------------------------------------
extern "C" void kernel_launch(void* const* d_in, const int* in_sizes, int n_in,
                              void* d_out, int out_size)
{
    (void)in_sizes; (void)n_in; (void)out_size;
    const float* x  = (const float*)d_in[0];
    const float* Wq = (const float*)d_in[1];
    const float* Wk = (const float*)d_in[2];
    const float* Wv = (const float*)d_in[3];
    const float* Wo = (const float*)d_in[4];
    const float* wf = (const float*)d_in[5];
    const float* wp = (const float*)d_in[6];
    float* out = (float*)d_out;

    cudaFuncSetAttribute(gemm_qkv, cudaFuncAttributeMaxDynamicSharedMemorySize, SMEM_GEMM4);
    cudaFuncSetAttribute(gemm_out, cudaFuncAttributeMaxDynamicSharedMemorySize, SMEM_GEMM2);
    cudaFuncSetAttribute(wave_attn_tc, cudaFuncAttributeMaxDynamicSharedMemorySize, SMEM_ATTN);

    // one-time fp32 -> fp16 conversion of all inputs (single launch)
    to_fp16_all<<<(CV_TOT + 255) / 256, 256>>>(x, Wq, Wk, Wv, Wo);

    gemm_qkv<<<dim3(8, 32, 3), 256, SMEM_GEMM4>>>();

    wave_attn_tc<<<dim3(16, 32), 128, SMEM_ATTN>>>(wf, wp);

    gemm_out<<<dim3(8, 64), 256, SMEM_GEMM2>>>(out);
}